// round 1
// baseline (speedup 1.0000x reference)
#include <cuda_runtime.h>

// ---------------------------------------------------------------------------
// AttentionHeadVDP: B=2, S=1024, D=1024, H=16, dh=64, fp32
// out[0:2M)   = x + attn_mu
// out[2M:4M)  = attn_var
// ---------------------------------------------------------------------------

#define B_  2
#define S_  1024
#define D_  1024
#define H_  16
#define DH_ 64

static const long long SZ_TOK = (long long)B_ * S_ * D_;   // 2,097,152
static const long long SZ_W   = (long long)D_ * D_;        // 1,048,576
static const long long SZ_ATT = (long long)B_ * H_ * S_ * S_; // 33,554,432

// scratch layout (floats)
#define OFF_Q    (0LL * SZ_TOK)
#define OFF_VQ   (1LL * SZ_TOK)
#define OFF_K    (2LL * SZ_TOK)
#define OFF_VK   (3LL * SZ_TOK)
#define OFF_V    (4LL * SZ_TOK)
#define OFF_VV   (5LL * SZ_TOK)
#define OFF_X2   (6LL * SZ_TOK)
#define OFF_Q2   (7LL * SZ_TOK)
#define OFF_VKK  (8LL * SZ_TOK)
#define OFF_VVV  (9LL * SZ_TOK)
#define OFF_WVPQ (10LL * SZ_TOK)
#define OFF_WVPK (OFF_WVPQ + SZ_W)
#define OFF_WVPV (OFF_WVPK + SZ_W)
#define OFF_S    (OFF_WVPV + SZ_W)
#define OFF_VS   (OFF_S + SZ_ATT)
#define OFF_G    (OFF_VS + SZ_ATT)
#define SCRATCH_TOTAL (OFF_G + SZ_ATT)

__device__ float g_scratch[SCRATCH_TOTAL];

// ---------------------------------------------------------------------------
// elementwise helpers
// ---------------------------------------------------------------------------
__global__ void ew_square_k(float* __restrict__ y, const float* __restrict__ x, int n) {
    int i = blockIdx.x * blockDim.x + threadIdx.x;
    if (i < n) { float v = x[i]; y[i] = v * v; }
}

// y = a + b*b
__global__ void ew_addsq_k(float* __restrict__ y, const float* __restrict__ a,
                           const float* __restrict__ b, int n) {
    int i = blockIdx.x * blockDim.x + threadIdx.x;
    if (i < n) { float bv = b[i]; y[i] = a[i] + bv * bv; }
}

// ---------------------------------------------------------------------------
// softmax-VDP: per row of 1024.  S <- p ; G <- (p(1-p))^2 * VS ; VS <- p^2
// grid: (1024 rows, 32 bh), 256 threads
// ---------------------------------------------------------------------------
__global__ __launch_bounds__(256)
void softmax_vdp_k(float* __restrict__ Sb, float* __restrict__ VSb, float* __restrict__ Gb) {
    __shared__ float red[256];
    const int tid = threadIdx.x;
    const long long base = (long long)blockIdx.y * (S_ * S_) + (long long)blockIdx.x * S_;
    float v[4];
    float mx = -1e30f;
#pragma unroll
    for (int i = 0; i < 4; i++) {
        v[i] = Sb[base + tid + i * 256];
        mx = fmaxf(mx, v[i]);
    }
    red[tid] = mx; __syncthreads();
    for (int s = 128; s > 0; s >>= 1) {
        if (tid < s) red[tid] = fmaxf(red[tid], red[tid + s]);
        __syncthreads();
    }
    mx = red[0]; __syncthreads();
    float sum = 0.f;
#pragma unroll
    for (int i = 0; i < 4; i++) { v[i] = __expf(v[i] - mx); sum += v[i]; }
    red[tid] = sum; __syncthreads();
    for (int s = 128; s > 0; s >>= 1) {
        if (tid < s) red[tid] += red[tid + s];
        __syncthreads();
    }
    const float inv = 1.0f / red[0];
#pragma unroll
    for (int i = 0; i < 4; i++) {
        const long long idx = base + tid + i * 256;
        const float p = v[i] * inv;
        const float pm = p * (1.0f - p);
        const float vs = VSb[idx];
        Sb[idx]  = p;
        Gb[idx]  = pm * pm * vs;
        VSb[idx] = p * p;
    }
}

// ---------------------------------------------------------------------------
// Tiled (dual) SGEMM.
//   TB=true :  C = alpha*(A1 @ B1^T [+ A2 @ B2^T]),  B is [N,K] row-major
//   TB=false:  C = alpha*(A1 @ B1   [+ A2 @ B2  ]),  B is [K,N] row-major
// Optional addend (same indexing as C). Batched over blockIdx.z -> (b,h) with
// per-operand offsets  off = b*sb + h*sh.
// 256 threads. BK == 8 assumed. TM,TN multiples of 4.
// ---------------------------------------------------------------------------
template<int BM, int BN, int BK, int TM, int TN, bool TB, bool DUAL>
__global__ __launch_bounds__(256)
void gemm_k(const float* __restrict__ A1, const float* __restrict__ B1,
            const float* __restrict__ A2, const float* __restrict__ B2,
            const float* __restrict__ add, float* __restrict__ C,
            int K, int lda, int ldb, int ldc,
            long long sbA, long long shA, long long sbB, long long shB,
            long long sbC, long long shC, float alpha)
{
    const int tid = threadIdx.x;
    const int bz = blockIdx.z;
    const int bb = bz >> 4, hh = bz & 15;
    const long long offA = (long long)bb * sbA + (long long)hh * shA;
    const long long offB = (long long)bb * sbB + (long long)hh * shB;
    const long long offC = (long long)bb * sbC + (long long)hh * shC;
    A1 += offA; B1 += offB; C += offC;
    if (DUAL) { A2 += offA; B2 += offB; }
    if (add) add += offC;

    const int m0 = blockIdx.y * BM;
    const int n0 = blockIdx.x * BN;

    __shared__ float As[DUAL ? 2 : 1][BK][BM];
    __shared__ float Bs[DUAL ? 2 : 1][BK][BN];

    const int rowBase = (tid / (BN / TN)) * TM;
    const int colBase = (tid % (BN / TN)) * TN;

    float acc[TM][TN];
#pragma unroll
    for (int i = 0; i < TM; i++)
#pragma unroll
        for (int j = 0; j < TN; j++) acc[i][j] = 0.f;

    // A loader: BM x BK tile, float4 along K, transposed store
    const int aRow = tid / (BK / 4);
    const int aK   = (tid % (BK / 4)) * 4;

    for (int k0 = 0; k0 < K; k0 += BK) {
        __syncthreads();
        if (BM * (BK / 4) == 256 || tid < BM * (BK / 4)) {
            float4 va = *(const float4*)(A1 + (long long)(m0 + aRow) * lda + k0 + aK);
            As[0][aK + 0][aRow] = va.x; As[0][aK + 1][aRow] = va.y;
            As[0][aK + 2][aRow] = va.z; As[0][aK + 3][aRow] = va.w;
            if (DUAL) {
                float4 vb = *(const float4*)(A2 + (long long)(m0 + aRow) * lda + k0 + aK);
                As[1][aK + 0][aRow] = vb.x; As[1][aK + 1][aRow] = vb.y;
                As[1][aK + 2][aRow] = vb.z; As[1][aK + 3][aRow] = vb.w;
            }
        }
        if (TB) {
            const int bRow = tid / (BK / 4);
            const int bK   = (tid % (BK / 4)) * 4;
            if (BN * (BK / 4) == 256 || tid < BN * (BK / 4)) {
                float4 v1 = *(const float4*)(B1 + (long long)(n0 + bRow) * ldb + k0 + bK);
                Bs[0][bK + 0][bRow] = v1.x; Bs[0][bK + 1][bRow] = v1.y;
                Bs[0][bK + 2][bRow] = v1.z; Bs[0][bK + 3][bRow] = v1.w;
                if (DUAL) {
                    float4 v2 = *(const float4*)(B2 + (long long)(n0 + bRow) * ldb + k0 + bK);
                    Bs[1][bK + 0][bRow] = v2.x; Bs[1][bK + 1][bRow] = v2.y;
                    Bs[1][bK + 2][bRow] = v2.z; Bs[1][bK + 3][bRow] = v2.w;
                }
            }
        } else {
            const int bR = tid / (BN / 4);
            const int bC = (tid % (BN / 4)) * 4;
            if (BK * (BN / 4) == 256 || tid < BK * (BN / 4)) {
                *(float4*)&Bs[0][bR][bC] =
                    *(const float4*)(B1 + (long long)(k0 + bR) * ldb + n0 + bC);
                if (DUAL) {
                    *(float4*)&Bs[1][bR][bC] =
                        *(const float4*)(B2 + (long long)(k0 + bR) * ldb + n0 + bC);
                }
            }
        }
        __syncthreads();
#pragma unroll
        for (int kk = 0; kk < BK; kk++) {
            float af[TM], bf[TN];
#pragma unroll
            for (int i = 0; i < TM; i += 4)
                *(float4*)&af[i] = *(const float4*)&As[0][kk][rowBase + i];
#pragma unroll
            for (int j = 0; j < TN; j += 4)
                *(float4*)&bf[j] = *(const float4*)&Bs[0][kk][colBase + j];
#pragma unroll
            for (int i = 0; i < TM; i++)
#pragma unroll
                for (int j = 0; j < TN; j++)
                    acc[i][j] += af[i] * bf[j];
            if (DUAL) {
                float af2[TM], bf2[TN];
#pragma unroll
                for (int i = 0; i < TM; i += 4)
                    *(float4*)&af2[i] = *(const float4*)&As[1][kk][rowBase + i];
#pragma unroll
                for (int j = 0; j < TN; j += 4)
                    *(float4*)&bf2[j] = *(const float4*)&Bs[1][kk][colBase + j];
#pragma unroll
                for (int i = 0; i < TM; i++)
#pragma unroll
                    for (int j = 0; j < TN; j++)
                        acc[i][j] += af2[i] * bf2[j];
            }
        }
    }

#pragma unroll
    for (int i = 0; i < TM; i++) {
        const long long r = m0 + rowBase + i;
#pragma unroll
        for (int j = 0; j < TN; j++) {
            const long long idx = r * ldc + n0 + colBase + j;
            float val = alpha * acc[i][j];
            if (add) val += add[idx];
            C[idx] = val;
        }
    }
}

// ---------------------------------------------------------------------------
// host orchestration
// ---------------------------------------------------------------------------
extern "C" void kernel_launch(void* const* d_in, const int* in_sizes, int n_in,
                              void* d_out, int out_size)
{
    (void)in_sizes; (void)n_in; (void)out_size;
    const float* x      = (const float*)d_in[0];
    const float* var_x  = (const float*)d_in[1];
    const float* wq_mu  = (const float*)d_in[2];
    const float* wq_var = (const float*)d_in[3];
    const float* wk_mu  = (const float*)d_in[4];
    const float* wk_var = (const float*)d_in[5];
    const float* wv_mu  = (const float*)d_in[6];
    const float* wv_var = (const float*)d_in[7];
    float* out = (float*)d_out;

    float* scr = nullptr;
    cudaGetSymbolAddress((void**)&scr, g_scratch);

    float* q    = scr + OFF_Q;
    float* vq   = scr + OFF_VQ;
    float* kk_  = scr + OFF_K;
    float* vk   = scr + OFF_VK;
    float* v    = scr + OFF_V;
    float* vv   = scr + OFF_VV;
    float* x2   = scr + OFF_X2;
    float* q2   = scr + OFF_Q2;
    float* vkk  = scr + OFF_VKK;
    float* vvv  = scr + OFF_VVV;
    float* wvpq = scr + OFF_WVPQ;
    float* wvpk = scr + OFF_WVPK;
    float* wvpv = scr + OFF_WVPV;
    float* Sb   = scr + OFF_S;
    float* VSb  = scr + OFF_VS;
    float* Gb   = scr + OFF_G;

    const int nTok = (int)SZ_TOK, nW = (int)SZ_W;
    const int EW = 256;

    // ---- prep: x^2, wvar + wmu^2 ----
    ew_square_k<<<(nTok + EW - 1) / EW, EW>>>(x2, x, nTok);
    ew_addsq_k<<<(nW + EW - 1) / EW, EW>>>(wvpq, wq_var, wq_mu, nW);
    ew_addsq_k<<<(nW + EW - 1) / EW, EW>>>(wvpk, wk_var, wk_mu, nW);
    ew_addsq_k<<<(nW + EW - 1) / EW, EW>>>(wvpv, wv_var, wv_mu, nW);

    // ---- projections: [2048,1024] = [2048,1024] @ [1024,1024]^T ----
    dim3 gP(D_ / 128, (B_ * S_) / 128, 1);
    gemm_k<128,128,8,8,8,true,false><<<gP, 256>>>(
        x, wq_mu, nullptr, nullptr, nullptr, q, D_, D_, D_, D_, 0,0,0,0,0,0, 1.f);
    gemm_k<128,128,8,8,8,true,true><<<gP, 256>>>(
        var_x, wvpq, x2, wq_var, nullptr, vq, D_, D_, D_, D_, 0,0,0,0,0,0, 1.f);
    gemm_k<128,128,8,8,8,true,false><<<gP, 256>>>(
        x, wk_mu, nullptr, nullptr, nullptr, kk_, D_, D_, D_, D_, 0,0,0,0,0,0, 1.f);
    gemm_k<128,128,8,8,8,true,true><<<gP, 256>>>(
        var_x, wvpk, x2, wk_var, nullptr, vk, D_, D_, D_, D_, 0,0,0,0,0,0, 1.f);
    gemm_k<128,128,8,8,8,true,false><<<gP, 256>>>(
        x, wv_mu, nullptr, nullptr, nullptr, v, D_, D_, D_, D_, 0,0,0,0,0,0, 1.f);
    gemm_k<128,128,8,8,8,true,true><<<gP, 256>>>(
        var_x, wvpv, x2, wv_var, nullptr, vv, D_, D_, D_, D_, 0,0,0,0,0,0, 1.f);

    // ---- q^2, vk + k^2, vv + v^2 ----
    ew_square_k<<<(nTok + EW - 1) / EW, EW>>>(q2, q, nTok);
    ew_addsq_k<<<(nTok + EW - 1) / EW, EW>>>(vkk, vk, kk_, nTok);
    ew_addsq_k<<<(nTok + EW - 1) / EW, EW>>>(vvv, vv, v, nTok);

    // ---- scores: per (b,h):  S = (q_h @ k_h^T)/32 ; VS = (vq@vkk^T + q2@vk^T)/1024 ----
    const long long sbH = (long long)S_ * D_;  // head-split batch stride
    const long long shH = DH_;                 // head-split head stride
    const long long sbF = (long long)H_ * S_ * S_; // flat batch stride
    const long long shF = (long long)S_ * S_;      // flat head stride
    dim3 gS(S_ / 128, S_ / 128, B_ * H_);
    gemm_k<128,128,8,8,8,true,false><<<gS, 256>>>(
        q, kk_, nullptr, nullptr, nullptr, Sb, DH_, D_, D_, S_,
        sbH, shH, sbH, shH, sbF, shF, 1.0f / 32.0f);
    gemm_k<128,128,8,8,8,true,true><<<gS, 256>>>(
        vq, vkk, q2, vk, nullptr, VSb, DH_, D_, D_, S_,
        sbH, shH, sbH, shH, sbF, shF, 1.0f / 1024.0f);

    // ---- softmax VDP: S<-p, G<-(p(1-p))^2*VS, VS<-p^2 ----
    softmax_vdp_k<<<dim3(S_, B_ * H_), 256>>>(Sb, VSb, Gb);

    // ---- AV: out_mu = x + p @ v_h ; out_var = g @ vvv_h + p^2 @ vv_h ----
    dim3 gAV(DH_ / 64, S_ / 128, B_ * H_);
    gemm_k<128,64,8,8,4,false,false><<<gAV, 256>>>(
        Sb, v, nullptr, nullptr, x, out, S_, S_, D_, D_,
        sbF, shF, sbH, shH, sbH, shH, 1.f);
    gemm_k<128,64,8,8,4,false,true><<<gAV, 256>>>(
        Gb, vvv, VSb, vv, nullptr, out + SZ_TOK, S_, S_, D_, D_,
        sbF, shF, sbH, shH, sbH, shH, 1.f);
}

// round 2
// speedup vs baseline: 1.1427x; 1.1427x over previous
#include <cuda_runtime.h>

// ---------------------------------------------------------------------------
// AttentionHeadVDP: B=2, S=1024, D=1024, H=16, dh=64, fp32
// out[0:2M)   = x + attn_mu
// out[2M:4M)  = attn_var
// R2: packed f32x2 FMA (FFMA2) inner loop + double-buffered smem pipeline
// ---------------------------------------------------------------------------

#define B_  2
#define S_  1024
#define D_  1024
#define H_  16
#define DH_ 64

static const long long SZ_TOK = (long long)B_ * S_ * D_;      // 2,097,152
static const long long SZ_W   = (long long)D_ * D_;           // 1,048,576
static const long long SZ_ATT = (long long)B_ * H_ * S_ * S_; // 33,554,432

#define OFF_Q    (0LL * SZ_TOK)
#define OFF_VQ   (1LL * SZ_TOK)
#define OFF_K    (2LL * SZ_TOK)
#define OFF_VK   (3LL * SZ_TOK)
#define OFF_V    (4LL * SZ_TOK)
#define OFF_VV   (5LL * SZ_TOK)
#define OFF_X2   (6LL * SZ_TOK)
#define OFF_Q2   (7LL * SZ_TOK)
#define OFF_VKK  (8LL * SZ_TOK)
#define OFF_VVV  (9LL * SZ_TOK)
#define OFF_WVPQ (10LL * SZ_TOK)
#define OFF_WVPK (OFF_WVPQ + SZ_W)
#define OFF_WVPV (OFF_WVPK + SZ_W)
#define OFF_S    (OFF_WVPV + SZ_W)
#define OFF_VS   (OFF_S + SZ_ATT)
#define OFF_G    (OFF_VS + SZ_ATT)
#define SCRATCH_TOTAL (OFF_G + SZ_ATT)

__device__ float g_scratch[SCRATCH_TOTAL];

// ---------------------------------------------------------------------------
// packed f32x2 helpers (FFMA2 — only reachable via PTX)
// ---------------------------------------------------------------------------
typedef unsigned long long ull_t;

__device__ __forceinline__ ull_t pack2(float lo, float hi) {
    ull_t r;
    asm("mov.b64 %0, {%1, %2};" : "=l"(r) : "f"(lo), "f"(hi));
    return r;
}
__device__ __forceinline__ void unpack2(ull_t v, float& lo, float& hi) {
    asm("mov.b64 {%0, %1}, %2;" : "=f"(lo), "=f"(hi) : "l"(v));
}
__device__ __forceinline__ ull_t fma2(ull_t a, ull_t b, ull_t c) {
    ull_t d;
    asm("fma.rn.f32x2 %0, %1, %2, %3;" : "=l"(d) : "l"(a), "l"(b), "l"(c));
    return d;
}

// ---------------------------------------------------------------------------
// elementwise helpers (float4)
// ---------------------------------------------------------------------------
__global__ void ew_square_k(float4* __restrict__ y, const float4* __restrict__ x, int n4) {
    int i = blockIdx.x * blockDim.x + threadIdx.x;
    if (i < n4) {
        float4 v = x[i];
        y[i] = make_float4(v.x * v.x, v.y * v.y, v.z * v.z, v.w * v.w);
    }
}

// y = a + b*b
__global__ void ew_addsq_k(float4* __restrict__ y, const float4* __restrict__ a,
                           const float4* __restrict__ b, int n4) {
    int i = blockIdx.x * blockDim.x + threadIdx.x;
    if (i < n4) {
        float4 av = a[i], bv = b[i];
        y[i] = make_float4(fmaf(bv.x, bv.x, av.x), fmaf(bv.y, bv.y, av.y),
                           fmaf(bv.z, bv.z, av.z), fmaf(bv.w, bv.w, av.w));
    }
}

// ---------------------------------------------------------------------------
// softmax-VDP: per row of 1024.  S <- p ; G <- (p(1-p))^2 * VS ; VS <- p^2
// ---------------------------------------------------------------------------
__global__ __launch_bounds__(256)
void softmax_vdp_k(float* __restrict__ Sb, float* __restrict__ VSb, float* __restrict__ Gb) {
    __shared__ float red[256];
    const int tid = threadIdx.x;
    const long long base = (long long)blockIdx.y * (S_ * S_) + (long long)blockIdx.x * S_;
    float v[4];
    float mx = -1e30f;
#pragma unroll
    for (int i = 0; i < 4; i++) {
        v[i] = Sb[base + tid + i * 256];
        mx = fmaxf(mx, v[i]);
    }
    red[tid] = mx; __syncthreads();
    for (int s = 128; s > 0; s >>= 1) {
        if (tid < s) red[tid] = fmaxf(red[tid], red[tid + s]);
        __syncthreads();
    }
    mx = red[0]; __syncthreads();
    float sum = 0.f;
#pragma unroll
    for (int i = 0; i < 4; i++) { v[i] = __expf(v[i] - mx); sum += v[i]; }
    red[tid] = sum; __syncthreads();
    for (int s = 128; s > 0; s >>= 1) {
        if (tid < s) red[tid] += red[tid + s];
        __syncthreads();
    }
    const float inv = 1.0f / red[0];
#pragma unroll
    for (int i = 0; i < 4; i++) {
        const long long idx = base + tid + i * 256;
        const float p = v[i] * inv;
        const float pm = p * (1.0f - p);
        const float vs = VSb[idx];
        Sb[idx]  = p;
        Gb[idx]  = pm * pm * vs;
        VSb[idx] = p * p;
    }
}

// ---------------------------------------------------------------------------
// Tiled (dual) SGEMM with FFMA2 inner loop and double-buffered smem.
//   TB=true :  C = alpha*(A1 @ B1^T [+ A2 @ B2^T]),  B is [N,K] row-major
//   TB=false:  C = alpha*(A1 @ B1   [+ A2 @ B2  ]),  B is [K,N] row-major
// Batched over blockIdx.z -> (b,h). 256 threads, BK==8, TM mult of 4, TN even.
// ---------------------------------------------------------------------------
template<int BM, int BN, int BK, int TM, int TN, bool TB, bool DUAL>
__global__ __launch_bounds__(256, 2)
void gemm_k(const float* __restrict__ A1, const float* __restrict__ B1,
            const float* __restrict__ A2, const float* __restrict__ B2,
            const float* __restrict__ add, float* __restrict__ C,
            int K, int lda, int ldb, int ldc,
            long long sbA, long long shA, long long sbB, long long shB,
            long long sbC, long long shC, float alpha)
{
    constexpr int NMAT = DUAL ? 2 : 1;
    constexpr int TN2  = TN / 2;

    const int tid = threadIdx.x;
    const int bz = blockIdx.z;
    const int bb = bz >> 4, hh = bz & 15;
    const long long offA = (long long)bb * sbA + (long long)hh * shA;
    const long long offB = (long long)bb * sbB + (long long)hh * shB;
    const long long offC = (long long)bb * sbC + (long long)hh * shC;
    A1 += offA; B1 += offB; C += offC;
    if (DUAL) { A2 += offA; B2 += offB; }
    if (add) add += offC;

    const int m0 = blockIdx.y * BM;
    const int n0 = blockIdx.x * BN;

    __shared__ float As[2][NMAT][BK][BM];
    __shared__ float Bs[2][NMAT][BK][BN];

    const int rowBase = (tid / (BN / TN)) * TM;
    const int colBase = (tid % (BN / TN)) * TN;

    // loaders
    const int aRow = tid / (BK / 4);
    const int aK   = (tid % (BK / 4)) * 4;
    const bool aAct = (BM * (BK / 4) == 256) || (tid < BM * (BK / 4));
    // TB B loader (BN x BK)
    const int btRow = tid / (BK / 4);
    const int btK   = (tid % (BK / 4)) * 4;
    const bool btAct = (BN * (BK / 4) == 256) || (tid < BN * (BK / 4));
    // non-TB B loader (BK x BN)
    const int bnR = tid / (BN / 4);
    const int bnC = (tid % (BN / 4)) * 4;
    const bool bnAct = (BK * (BN / 4) == 256) || (tid < BK * (BN / 4));

    float4 rA[NMAT], rB[NMAT];

    auto loadRegs = [&](int k0) {
        if (aAct) {
            rA[0] = *(const float4*)(A1 + (long long)(m0 + aRow) * lda + k0 + aK);
            if (DUAL) rA[1] = *(const float4*)(A2 + (long long)(m0 + aRow) * lda + k0 + aK);
        }
        if (TB) {
            if (btAct) {
                rB[0] = *(const float4*)(B1 + (long long)(n0 + btRow) * ldb + k0 + btK);
                if (DUAL) rB[1] = *(const float4*)(B2 + (long long)(n0 + btRow) * ldb + k0 + btK);
            }
        } else {
            if (bnAct) {
                rB[0] = *(const float4*)(B1 + (long long)(k0 + bnR) * ldb + n0 + bnC);
                if (DUAL) rB[1] = *(const float4*)(B2 + (long long)(k0 + bnR) * ldb + n0 + bnC);
            }
        }
    };
    auto storeSmem = [&](int buf) {
        if (aAct) {
#pragma unroll
            for (int m = 0; m < NMAT; m++) {
                As[buf][m][aK + 0][aRow] = rA[m].x;
                As[buf][m][aK + 1][aRow] = rA[m].y;
                As[buf][m][aK + 2][aRow] = rA[m].z;
                As[buf][m][aK + 3][aRow] = rA[m].w;
            }
        }
        if (TB) {
            if (btAct) {
#pragma unroll
                for (int m = 0; m < NMAT; m++) {
                    Bs[buf][m][btK + 0][btRow] = rB[m].x;
                    Bs[buf][m][btK + 1][btRow] = rB[m].y;
                    Bs[buf][m][btK + 2][btRow] = rB[m].z;
                    Bs[buf][m][btK + 3][btRow] = rB[m].w;
                }
            }
        } else {
            if (bnAct) {
#pragma unroll
                for (int m = 0; m < NMAT; m++)
                    *(float4*)&Bs[buf][m][bnR][bnC] = rB[m];
            }
        }
    };

    ull_t acc[TM][TN2];
#pragma unroll
    for (int i = 0; i < TM; i++)
#pragma unroll
        for (int j = 0; j < TN2; j++) acc[i][j] = 0ull;

    loadRegs(0);
    storeSmem(0);
    __syncthreads();

    int buf = 0;
    for (int k0 = 0; k0 < K; k0 += BK) {
        const bool hasNext = (k0 + BK < K);
        if (hasNext) loadRegs(k0 + BK);

#pragma unroll
        for (int kk = 0; kk < BK; kk++) {
#pragma unroll
            for (int m = 0; m < NMAT; m++) {
                float af[TM];
                ull_t bp[TN2];
#pragma unroll
                for (int i = 0; i < TM; i += 4)
                    *(float4*)&af[i] = *(const float4*)&As[buf][m][kk][rowBase + i];
#pragma unroll
                for (int j = 0; j < TN2; j++)
                    bp[j] = *(const ull_t*)&Bs[buf][m][kk][colBase + 2 * j];
#pragma unroll
                for (int i = 0; i < TM; i++) {
                    const ull_t a2 = pack2(af[i], af[i]);
#pragma unroll
                    for (int j = 0; j < TN2; j++)
                        acc[i][j] = fma2(a2, bp[j], acc[i][j]);
                }
            }
        }

        if (hasNext) {
            storeSmem(buf ^ 1);
            __syncthreads();
            buf ^= 1;
        }
    }

#pragma unroll
    for (int i = 0; i < TM; i++) {
        const long long r = m0 + rowBase + i;
#pragma unroll
        for (int j = 0; j < TN2; j++) {
            const long long idx = r * ldc + n0 + colBase + 2 * j;
            float lo, hi;
            unpack2(acc[i][j], lo, hi);
            float2 val;
            val.x = alpha * lo;
            val.y = alpha * hi;
            if (add) {
                val.x += add[idx];
                val.y += add[idx + 1];
            }
            *(float2*)&C[idx] = val;
        }
    }
}

// ---------------------------------------------------------------------------
// host orchestration
// ---------------------------------------------------------------------------
extern "C" void kernel_launch(void* const* d_in, const int* in_sizes, int n_in,
                              void* d_out, int out_size)
{
    (void)in_sizes; (void)n_in; (void)out_size;
    const float* x      = (const float*)d_in[0];
    const float* var_x  = (const float*)d_in[1];
    const float* wq_mu  = (const float*)d_in[2];
    const float* wq_var = (const float*)d_in[3];
    const float* wk_mu  = (const float*)d_in[4];
    const float* wk_var = (const float*)d_in[5];
    const float* wv_mu  = (const float*)d_in[6];
    const float* wv_var = (const float*)d_in[7];
    float* out = (float*)d_out;

    float* scr = nullptr;
    cudaGetSymbolAddress((void**)&scr, g_scratch);

    float* q    = scr + OFF_Q;
    float* vq   = scr + OFF_VQ;
    float* kk_  = scr + OFF_K;
    float* vk   = scr + OFF_VK;
    float* v    = scr + OFF_V;
    float* vv   = scr + OFF_VV;
    float* x2   = scr + OFF_X2;
    float* q2   = scr + OFF_Q2;
    float* vkk  = scr + OFF_VKK;
    float* vvv  = scr + OFF_VVV;
    float* wvpq = scr + OFF_WVPQ;
    float* wvpk = scr + OFF_WVPK;
    float* wvpv = scr + OFF_WVPV;
    float* Sb   = scr + OFF_S;
    float* VSb  = scr + OFF_VS;
    float* Gb   = scr + OFF_G;

    const int nTok4 = (int)(SZ_TOK / 4), nW4 = (int)(SZ_W / 4);
    const int EW = 256;

    // ---- prep: x^2, wvar + wmu^2 ----
    ew_square_k<<<(nTok4 + EW - 1) / EW, EW>>>((float4*)x2, (const float4*)x, nTok4);
    ew_addsq_k<<<(nW4 + EW - 1) / EW, EW>>>((float4*)wvpq, (const float4*)wq_var, (const float4*)wq_mu, nW4);
    ew_addsq_k<<<(nW4 + EW - 1) / EW, EW>>>((float4*)wvpk, (const float4*)wk_var, (const float4*)wk_mu, nW4);
    ew_addsq_k<<<(nW4 + EW - 1) / EW, EW>>>((float4*)wvpv, (const float4*)wv_var, (const float4*)wv_mu, nW4);

    // ---- projections: [2048,1024] = [2048,1024] @ [1024,1024]^T ----
    dim3 gP(D_ / 128, (B_ * S_) / 128, 1);
    gemm_k<128,128,8,8,8,true,false><<<gP, 256>>>(
        x, wq_mu, nullptr, nullptr, nullptr, q, D_, D_, D_, D_, 0,0,0,0,0,0, 1.f);
    gemm_k<128,128,8,8,8,true,true><<<gP, 256>>>(
        var_x, wvpq, x2, wq_var, nullptr, vq, D_, D_, D_, D_, 0,0,0,0,0,0, 1.f);
    gemm_k<128,128,8,8,8,true,false><<<gP, 256>>>(
        x, wk_mu, nullptr, nullptr, nullptr, kk_, D_, D_, D_, D_, 0,0,0,0,0,0, 1.f);
    gemm_k<128,128,8,8,8,true,true><<<gP, 256>>>(
        var_x, wvpk, x2, wk_var, nullptr, vk, D_, D_, D_, D_, 0,0,0,0,0,0, 1.f);
    gemm_k<128,128,8,8,8,true,false><<<gP, 256>>>(
        x, wv_mu, nullptr, nullptr, nullptr, v, D_, D_, D_, D_, 0,0,0,0,0,0, 1.f);
    gemm_k<128,128,8,8,8,true,true><<<gP, 256>>>(
        var_x, wvpv, x2, wv_var, nullptr, vv, D_, D_, D_, D_, 0,0,0,0,0,0, 1.f);

    // ---- q^2, vk + k^2, vv + v^2 ----
    ew_square_k<<<(nTok4 + EW - 1) / EW, EW>>>((float4*)q2, (const float4*)q, nTok4);
    ew_addsq_k<<<(nTok4 + EW - 1) / EW, EW>>>((float4*)vkk, (const float4*)vk, (const float4*)kk_, nTok4);
    ew_addsq_k<<<(nTok4 + EW - 1) / EW, EW>>>((float4*)vvv, (const float4*)vv, (const float4*)v, nTok4);

    // ---- scores: per (b,h):  S = (q_h @ k_h^T)/32 ; VS = (vq@vkk^T + q2@vk^T)/1024 ----
    const long long sbH = (long long)S_ * D_;
    const long long shH = DH_;
    const long long sbF = (long long)H_ * S_ * S_;
    const long long shF = (long long)S_ * S_;
    dim3 gS(S_ / 128, S_ / 128, B_ * H_);
    gemm_k<128,128,8,8,8,true,false><<<gS, 256>>>(
        q, kk_, nullptr, nullptr, nullptr, Sb, DH_, D_, D_, S_,
        sbH, shH, sbH, shH, sbF, shF, 1.0f / 32.0f);
    gemm_k<128,128,8,8,8,true,true><<<gS, 256>>>(
        vq, vkk, q2, vk, nullptr, VSb, DH_, D_, D_, S_,
        sbH, shH, sbH, shH, sbF, shF, 1.0f / 1024.0f);

    // ---- softmax VDP: S<-p, G<-(p(1-p))^2*VS, VS<-p^2 ----
    softmax_vdp_k<<<dim3(S_, B_ * H_), 256>>>(Sb, VSb, Gb);

    // ---- AV: out_mu = x + p @ v_h ; out_var = g @ vvv_h + p^2 @ vv_h ----
    dim3 gAV(DH_ / 64, S_ / 128, B_ * H_);
    gemm_k<128,64,8,8,4,false,false><<<gAV, 256>>>(
        Sb, v, nullptr, nullptr, x, out, S_, S_, D_, D_,
        sbF, shF, sbH, shH, sbH, shH, 1.f);
    gemm_k<128,64,8,8,4,false,true><<<gAV, 256>>>(
        Gb, vvv, VSb, vv, nullptr, out + SZ_TOK, S_, S_, D_, D_,
        sbF, shF, sbH, shH, sbH, shH, 1.f);
}

// round 4
// speedup vs baseline: 1.9066x; 1.6684x over previous
#include <cuda_runtime.h>
#include <cuda_bf16.h>
#include <cstdint>

typedef __nv_bfloat16 bf16;

// ---------------------------------------------------------------------------
// AttentionHeadVDP: B=2, S=1024, D=1024, H=16, dh=64, fp32
// R4: warp-level mma.sync bf16 (HMMA), hi/lo split on mu path, single bf16 var path
// ---------------------------------------------------------------------------
#define B_  2
#define S_  1024
#define D_  1024
#define H_  16
#define DH_ 64

static const long long SZ_TOK = 2097152LL;   // B*S*D
static const long long SZ_W   = 1048576LL;   // D*D
static const long long SZ_ATT = 33554432LL;  // B*H*S*S

// ---------------- bf16 scratch (elements) ----------------
// token-sized split arrays
#define O_XH    (0LL  * SZ_TOK)
#define O_XL    (1LL  * SZ_TOK)
#define O_QH    (2LL  * SZ_TOK)
#define O_QL    (3LL  * SZ_TOK)
#define O_KH    (4LL  * SZ_TOK)
#define O_KL    (5LL  * SZ_TOK)
#define O_VTH   (6LL  * SZ_TOK)   // v transposed [B][D][S]
#define O_VTL   (7LL  * SZ_TOK)
// token-sized single arrays (var path)
#define O_X2    (8LL  * SZ_TOK)
#define O_VX    (9LL  * SZ_TOK)
#define O_VQ    (10LL * SZ_TOK)
#define O_VK    (11LL * SZ_TOK)
#define O_VKK   (12LL * SZ_TOK)
#define O_Q2    (13LL * SZ_TOK)
#define O_VVT   (14LL * SZ_TOK)   // vv transposed
#define O_VVVT  (15LL * SZ_TOK)   // vvv transposed
#define WBASE   (16LL * SZ_TOK)
#define O_WQMH  (WBASE + 0LL  * SZ_W)
#define O_WQML  (WBASE + 1LL  * SZ_W)
#define O_WKMH  (WBASE + 2LL  * SZ_W)
#define O_WKML  (WBASE + 3LL  * SZ_W)
#define O_WVMH  (WBASE + 4LL  * SZ_W)
#define O_WVML  (WBASE + 5LL  * SZ_W)
#define O_WQV   (WBASE + 6LL  * SZ_W)
#define O_WQP   (WBASE + 7LL  * SZ_W)
#define O_WKV   (WBASE + 8LL  * SZ_W)
#define O_WKP   (WBASE + 9LL  * SZ_W)
#define O_WVV   (WBASE + 10LL * SZ_W)
#define O_WVP   (WBASE + 11LL * SZ_W)
#define ABASE   (WBASE + 12LL * SZ_W)
#define O_PH    (ABASE + 0LL * SZ_ATT)
#define O_PL    (ABASE + 1LL * SZ_ATT)
#define O_P2    (ABASE + 2LL * SZ_ATT)
#define O_G     (ABASE + 3LL * SZ_ATT)
#define BF_TOTAL (ABASE + 4LL * SZ_ATT)

__device__ bf16  g_bf[BF_TOTAL];
__device__ float g_sb[SZ_ATT];
__device__ float g_vsb[SZ_ATT];
__device__ float g_kf[SZ_TOK];
__device__ float g_vf[SZ_TOK];

// ---------------------------------------------------------------------------
// PTX helpers
// ---------------------------------------------------------------------------
__device__ __forceinline__ uint32_t smem_to_u32(const void* p) {
    uint32_t a;
    asm("{ .reg .u64 t; cvta.to.shared.u64 t, %1; cvt.u32.u64 %0, t; }" : "=r"(a) : "l"(p));
    return a;
}
__device__ __forceinline__ void cp16(uint32_t s, const void* g) {
    asm volatile("cp.async.cg.shared.global [%0], [%1], 16;" :: "r"(s), "l"(g) : "memory");
}
#define CP_COMMIT() asm volatile("cp.async.commit_group;" ::: "memory")
#define CP_WAIT(n)  asm volatile("cp.async.wait_group %0;" :: "n"(n) : "memory")

__device__ __forceinline__ void ldsm4(uint32_t* r, uint32_t addr) {
    asm volatile("ldmatrix.sync.aligned.m8n8.x4.shared.b16 {%0,%1,%2,%3}, [%4];"
        : "=r"(r[0]), "=r"(r[1]), "=r"(r[2]), "=r"(r[3]) : "r"(addr));
}
__device__ __forceinline__ void mma16816(float* c, const uint32_t* a, const uint32_t* b) {
    asm volatile(
        "mma.sync.aligned.m16n8k16.row.col.f32.bf16.bf16.f32 "
        "{%0,%1,%2,%3}, {%4,%5,%6,%7}, {%8,%9}, {%0,%1,%2,%3};"
        : "+f"(c[0]), "+f"(c[1]), "+f"(c[2]), "+f"(c[3])
        : "r"(a[0]), "r"(a[1]), "r"(a[2]), "r"(a[3]), "r"(b[0]), "r"(b[1]));
}

__device__ __forceinline__ void bsplit(float a, bf16* h, bf16* l) {
    bf16 hh = __float2bfloat16(a);
    *h = hh;
    *l = __float2bfloat16(a - __bfloat162float(hh));
}

// ---------------------------------------------------------------------------
// conversion kernels
// ---------------------------------------------------------------------------
__global__ void conv_x_k(const float* __restrict__ x, const float* __restrict__ vx, int n,
                         bf16* xh, bf16* xl, bf16* x2, bf16* vxo) {
    int i = blockIdx.x * blockDim.x + threadIdx.x;
    if (i < n) {
        float a = x[i];
        bsplit(a, xh + i, xl + i);
        x2[i]  = __float2bfloat16(a * a);
        vxo[i] = __float2bfloat16(vx[i]);
    }
}
__global__ void conv_w_k(const float* __restrict__ wmu, const float* __restrict__ wvar, int n,
                         bf16* mh, bf16* ml, bf16* wv, bf16* wp) {
    int i = blockIdx.x * blockDim.x + threadIdx.x;
    if (i < n) {
        float m = wmu[i], v = wvar[i];
        bsplit(m, mh + i, ml + i);
        wv[i] = __float2bfloat16(v);
        wp[i] = __float2bfloat16(fmaf(m, m, v));
    }
}

// ---------------------------------------------------------------------------
// softmax-VDP: reads Sb, VSb; writes ph/pl split + p2, g single bf16
// ---------------------------------------------------------------------------
__global__ __launch_bounds__(256)
void softmax_vdp_k(const float* __restrict__ Sb, const float* __restrict__ VSb,
                   bf16* ph, bf16* pl, bf16* p2, bf16* g) {
    __shared__ float red[256];
    const int tid = threadIdx.x;
    const long long base = (long long)blockIdx.y * (S_ * S_) + (long long)blockIdx.x * S_;
    float v[4];
    float mx = -1e30f;
#pragma unroll
    for (int i = 0; i < 4; i++) { v[i] = Sb[base + tid + i * 256]; mx = fmaxf(mx, v[i]); }
    red[tid] = mx; __syncthreads();
    for (int s = 128; s > 0; s >>= 1) { if (tid < s) red[tid] = fmaxf(red[tid], red[tid + s]); __syncthreads(); }
    mx = red[0]; __syncthreads();
    float sum = 0.f;
#pragma unroll
    for (int i = 0; i < 4; i++) { v[i] = __expf(v[i] - mx); sum += v[i]; }
    red[tid] = sum; __syncthreads();
    for (int s = 128; s > 0; s >>= 1) { if (tid < s) red[tid] += red[tid + s]; __syncthreads(); }
    const float inv = 1.0f / red[0];
#pragma unroll
    for (int i = 0; i < 4; i++) {
        const long long idx = base + tid + i * 256;
        const float p = v[i] * inv;
        const float pm = p * (1.0f - p);
        bsplit(p, ph + idx, pl + idx);
        p2[idx] = __float2bfloat16(p * p);
        g[idx]  = __float2bfloat16(pm * pm * VSb[idx]);
    }
}

// ---------------------------------------------------------------------------
// bf16 warp-MMA GEMM.
//   C[BMx BN] fp32 accum.  A mats [M,K] k-contig; B mats [N,K] k-contig.
//   MODE 0 (SPLIT3): A0=Ah,A1=Al,B0=Bh,B1=Bl; acc += AhBh + AlBh + AhBl
//   MODE 1 (DUAL2):  acc += A0@B0 + A1@B1
//   Batched over blockIdx.z -> (b,h).  Epilogue (runtime flags):
//     val = alpha*acc [+ addp];  cf fp32 store;  ch/cl split bf16;  cs single bf16;
//     ds = (auxmode==1 ? val^2 : val + auxf^2) single bf16;
//     transC: bf16 stores use transposed [B][D][S] indexing.
// ---------------------------------------------------------------------------
template<int BN, int MODE>
__global__ __launch_bounds__(256)
void gemm_mma_k(const bf16* __restrict__ A0, const bf16* __restrict__ A1,
                const bf16* __restrict__ B0, const bf16* __restrict__ B1,
                int K, int lda, int ldb, int ldc,
                long long sbA, long long shA, long long sbB, long long shB,
                long long sbC, long long shC,
                float alpha,
                float* __restrict__ cf, const float* __restrict__ addp,
                bf16* __restrict__ ch, bf16* __restrict__ cl,
                bf16* __restrict__ cs,
                const float* __restrict__ auxf, bf16* __restrict__ ds, int auxmode,
                int transC)
{
    constexpr int BM = 128, BK = 32, SK = 40;           // SK: padded row stride (bf16)
    constexpr int WARPS_N = (BN == 128) ? 4 : 2;
    constexpr int WARPS_M = 8 / WARPS_N;
    constexpr int WM = BM / WARPS_M, WN = BN / WARPS_N; // 64x32 or 32x32
    constexpr int MT = WM / 16, NT = WN / 8;
    constexpr int ATILE = BM * SK * 2;                  // bytes
    constexpr int BTILE = BN * SK * 2;
    constexpr int BUFB  = 2 * ATILE + 2 * BTILE;

    extern __shared__ char smem[];
    const uint32_t s32 = smem_to_u32(smem);
    const int tid = threadIdx.x;
    const int wid = tid >> 5, lane = tid & 31;
    const int wm = wid / WARPS_N, wn = wid % WARPS_N;

    const int bz = blockIdx.z, bb = bz >> 4, hh = bz & 15;
    const long long offA = (long long)bb * sbA + (long long)hh * shA;
    const long long offB = (long long)bb * sbB + (long long)hh * shB;
    const long long offC = (long long)bb * sbC + (long long)hh * shC;
    const int m0 = blockIdx.y * BM;
    const int n0 = blockIdx.x * BN;

    auto loadbuf = [&](int kc, int buf) {
        const int k0 = kc * BK;
        const uint32_t b32 = s32 + buf * BUFB;
#pragma unroll
        for (int i = 0; i < BM * 4 / 256; i++) {
            const int c = tid + i * 256;
            const int row = c >> 2, seg = c & 3;
            const long long go = offA + (long long)(m0 + row) * lda + k0 + seg * 8;
            const uint32_t so = (uint32_t)(row * SK + seg * 8) * 2;
            cp16(b32 + so, A0 + go);
            cp16(b32 + ATILE + so, A1 + go);
        }
#pragma unroll
        for (int i = 0; i < BN * 4 / 256; i++) {
            const int c = tid + i * 256;
            const int row = c >> 2, seg = c & 3;
            const long long go = offB + (long long)(n0 + row) * ldb + k0 + seg * 8;
            const uint32_t so = (uint32_t)(row * SK + seg * 8) * 2;
            cp16(b32 + 2 * ATILE + so, B0 + go);
            cp16(b32 + 2 * ATILE + BTILE + so, B1 + go);
        }
        CP_COMMIT();
    };

    float acc[MT][NT][4];
#pragma unroll
    for (int i = 0; i < MT; i++)
#pragma unroll
        for (int j = 0; j < NT; j++)
#pragma unroll
            for (int r = 0; r < 4; r++) acc[i][j][r] = 0.f;

    const int NKC = K / BK;
    loadbuf(0, 0);

    for (int kc = 0; kc < NKC; kc++) {
        const int buf = kc & 1;
        if (kc + 1 < NKC) { loadbuf(kc + 1, buf ^ 1); CP_WAIT(1); }
        else              { CP_WAIT(0); }
        __syncthreads();

        const uint32_t b32 = s32 + buf * BUFB;
#pragma unroll
        for (int kh = 0; kh < 2; kh++) {
            const int kcol = kh * 16 + (lane >> 4) * 8;
            uint32_t afr[2][MT][4];
            uint32_t bfr[2][NT][2];
#pragma unroll
            for (int mat = 0; mat < 2; mat++) {
#pragma unroll
                for (int mt = 0; mt < MT; mt++) {
                    const int row = wm * WM + mt * 16 + (lane & 15);
                    ldsm4(afr[mat][mt], b32 + mat * ATILE + (uint32_t)(row * SK + kcol) * 2);
                }
#pragma unroll
                for (int nt2 = 0; nt2 < NT / 2; nt2++) {
                    const int row = wn * WN + nt2 * 16 + (lane & 15);
                    uint32_t r[4];
                    ldsm4(r, b32 + 2 * ATILE + mat * BTILE + (uint32_t)(row * SK + kcol) * 2);
                    bfr[mat][2 * nt2][0]     = r[0]; bfr[mat][2 * nt2][1]     = r[2];
                    bfr[mat][2 * nt2 + 1][0] = r[1]; bfr[mat][2 * nt2 + 1][1] = r[3];
                }
            }
            // combo 1: A0 @ B0
#pragma unroll
            for (int mt = 0; mt < MT; mt++)
#pragma unroll
                for (int nt = 0; nt < NT; nt++)
                    mma16816(acc[mt][nt], afr[0][mt], bfr[0][nt]);
            if (MODE == 0) {
                // A1(lo) @ B0(hi)
#pragma unroll
                for (int mt = 0; mt < MT; mt++)
#pragma unroll
                    for (int nt = 0; nt < NT; nt++)
                        mma16816(acc[mt][nt], afr[1][mt], bfr[0][nt]);
                // A0(hi) @ B1(lo)
#pragma unroll
                for (int mt = 0; mt < MT; mt++)
#pragma unroll
                    for (int nt = 0; nt < NT; nt++)
                        mma16816(acc[mt][nt], afr[0][mt], bfr[1][nt]);
            } else {
                // A1 @ B1
#pragma unroll
                for (int mt = 0; mt < MT; mt++)
#pragma unroll
                    for (int nt = 0; nt < NT; nt++)
                        mma16816(acc[mt][nt], afr[1][mt], bfr[1][nt]);
            }
        }
        __syncthreads();
    }

    // ---- epilogue ----
#pragma unroll
    for (int mt = 0; mt < MT; mt++) {
#pragma unroll
        for (int nt = 0; nt < NT; nt++) {
#pragma unroll
            for (int rp = 0; rp < 2; rp++) {
                const int m = m0 + wm * WM + mt * 16 + (lane >> 2) + rp * 8;
                const int nbase = n0 + wn * WN + nt * 8 + (lane & 3) * 2;
#pragma unroll
                for (int cc = 0; cc < 2; cc++) {
                    const int n = nbase + cc;
                    float val = alpha * acc[mt][nt][rp * 2 + cc];
                    const long long idx = offC + (long long)m * ldc + n;
                    if (addp) val += addp[idx];
                    if (cf) cf[idx] = val;
                    const long long bidx = transC
                        ? ((long long)(m >> 10) * ((long long)D_ * S_) + (long long)n * S_ + (m & (S_ - 1)))
                        : idx;
                    if (ch) {
                        bf16 hv = __float2bfloat16(val);
                        ch[bidx] = hv;
                        cl[bidx] = __float2bfloat16(val - __bfloat162float(hv));
                    }
                    if (cs) cs[bidx] = __float2bfloat16(val);
                    if (auxmode) {
                        const float t = (auxmode == 1) ? val * val
                                                       : fmaf(auxf[idx], auxf[idx], val);
                        ds[bidx] = __float2bfloat16(t);
                    }
                }
            }
        }
    }
}

// ---------------------------------------------------------------------------
// host orchestration
// ---------------------------------------------------------------------------
extern "C" void kernel_launch(void* const* d_in, const int* in_sizes, int n_in,
                              void* d_out, int out_size)
{
    (void)in_sizes; (void)n_in; (void)out_size;
    const float* x      = (const float*)d_in[0];
    const float* var_x  = (const float*)d_in[1];
    const float* wq_mu  = (const float*)d_in[2];
    const float* wq_var = (const float*)d_in[3];
    const float* wk_mu  = (const float*)d_in[4];
    const float* wk_var = (const float*)d_in[5];
    const float* wv_mu  = (const float*)d_in[6];
    const float* wv_var = (const float*)d_in[7];
    float* out = (float*)d_out;

    bf16* bp = nullptr;   cudaGetSymbolAddress((void**)&bp, g_bf);
    float* sb = nullptr;  cudaGetSymbolAddress((void**)&sb, g_sb);
    float* vsb = nullptr; cudaGetSymbolAddress((void**)&vsb, g_vsb);
    float* kf = nullptr;  cudaGetSymbolAddress((void**)&kf, g_kf);
    float* vf = nullptr;  cudaGetSymbolAddress((void**)&vf, g_vf);

    const int SM128 = 2 * (2 * 10240 + 2 * 10240);  // 81920
    const int SM64  = 2 * (2 * 10240 + 2 * 5120);   // 61440
    cudaFuncSetAttribute(gemm_mma_k<128, 0>, cudaFuncAttributeMaxDynamicSharedMemorySize, SM128);
    cudaFuncSetAttribute(gemm_mma_k<128, 1>, cudaFuncAttributeMaxDynamicSharedMemorySize, SM128);
    cudaFuncSetAttribute(gemm_mma_k<64, 0>,  cudaFuncAttributeMaxDynamicSharedMemorySize, SM64);
    cudaFuncSetAttribute(gemm_mma_k<64, 1>,  cudaFuncAttributeMaxDynamicSharedMemorySize, SM64);

    // ---- conversions ----
    conv_x_k<<<(int)(SZ_TOK / 256), 256>>>(x, var_x, (int)SZ_TOK,
        bp + O_XH, bp + O_XL, bp + O_X2, bp + O_VX);
    conv_w_k<<<(int)(SZ_W / 256), 256>>>(wq_mu, wq_var, (int)SZ_W,
        bp + O_WQMH, bp + O_WQML, bp + O_WQV, bp + O_WQP);
    conv_w_k<<<(int)(SZ_W / 256), 256>>>(wk_mu, wk_var, (int)SZ_W,
        bp + O_WKMH, bp + O_WKML, bp + O_WKV, bp + O_WKP);
    conv_w_k<<<(int)(SZ_W / 256), 256>>>(wv_mu, wv_var, (int)SZ_W,
        bp + O_WVMH, bp + O_WVML, bp + O_WVV, bp + O_WVP);

    // ---- projections (unbatched, M=2048, N=1024, K=1024) ----
    dim3 gP(8, 16, 1);
    // q mu: split out qh/ql; q2 = c^2 (single)
    gemm_mma_k<128, 0><<<gP, 256, SM128>>>(
        bp + O_XH, bp + O_XL, bp + O_WQMH, bp + O_WQML,
        D_, D_, D_, D_, 0, 0, 0, 0, 0, 0, 1.f,
        nullptr, nullptr, bp + O_QH, bp + O_QL, nullptr,
        nullptr, bp + O_Q2, 1, 0);
    // k mu: split kh/kl + fp32 kf
    gemm_mma_k<128, 0><<<gP, 256, SM128>>>(
        bp + O_XH, bp + O_XL, bp + O_WKMH, bp + O_WKML,
        D_, D_, D_, D_, 0, 0, 0, 0, 0, 0, 1.f,
        kf, nullptr, bp + O_KH, bp + O_KL, nullptr,
        nullptr, nullptr, 0, 0);
    // v mu: split vTh/vTl transposed + fp32 vf (untransposed)
    gemm_mma_k<128, 0><<<gP, 256, SM128>>>(
        bp + O_XH, bp + O_XL, bp + O_WVMH, bp + O_WVML,
        D_, D_, D_, D_, 0, 0, 0, 0, 0, 0, 1.f,
        vf, nullptr, bp + O_VTH, bp + O_VTL, nullptr,
        nullptr, nullptr, 0, 1);
    // vq = vx@wqp^T + x2@wqv^T (single bf16)
    gemm_mma_k<128, 1><<<gP, 256, SM128>>>(
        bp + O_VX, bp + O_X2, bp + O_WQP, bp + O_WQV,
        D_, D_, D_, D_, 0, 0, 0, 0, 0, 0, 1.f,
        nullptr, nullptr, nullptr, nullptr, bp + O_VQ,
        nullptr, nullptr, 0, 0);
    // vk; vkk = vk + kf^2
    gemm_mma_k<128, 1><<<gP, 256, SM128>>>(
        bp + O_VX, bp + O_X2, bp + O_WKP, bp + O_WKV,
        D_, D_, D_, D_, 0, 0, 0, 0, 0, 0, 1.f,
        nullptr, nullptr, nullptr, nullptr, bp + O_VK,
        kf, bp + O_VKK, 2, 0);
    // vv (transposed) ; vvv = vv + vf^2 (transposed)
    gemm_mma_k<128, 1><<<gP, 256, SM128>>>(
        bp + O_VX, bp + O_X2, bp + O_WVP, bp + O_WVV,
        D_, D_, D_, D_, 0, 0, 0, 0, 0, 0, 1.f,
        nullptr, nullptr, nullptr, nullptr, bp + O_VVT,
        vf, bp + O_VVVT, 2, 1);

    // ---- scores: per (b,h), M=N=1024, K=64 ----
    const long long sbH = (long long)S_ * D_;
    const long long shH = DH_;
    const long long sbF = (long long)H_ * S_ * S_;
    const long long shF = (long long)S_ * S_;
    dim3 gS(8, 8, 32);
    gemm_mma_k<128, 0><<<gS, 256, SM128>>>(
        bp + O_QH, bp + O_QL, bp + O_KH, bp + O_KL,
        DH_, D_, D_, S_, sbH, shH, sbH, shH, sbF, shF, 1.0f / 32.0f,
        sb, nullptr, nullptr, nullptr, nullptr, nullptr, nullptr, 0, 0);
    gemm_mma_k<128, 1><<<gS, 256, SM128>>>(
        bp + O_VQ, bp + O_Q2, bp + O_VKK, bp + O_VK,
        DH_, D_, D_, S_, sbH, shH, sbH, shH, sbF, shF, 1.0f / 1024.0f,
        vsb, nullptr, nullptr, nullptr, nullptr, nullptr, nullptr, 0, 0);

    // ---- softmax VDP ----
    softmax_vdp_k<<<dim3(S_, B_ * H_), 256>>>(sb, vsb,
        bp + O_PH, bp + O_PL, bp + O_P2, bp + O_G);

    // ---- AV: per (b,h), M=1024, N=64, K=1024; B operands transposed [dh][S] ----
    const long long sbVT = (long long)D_ * S_;  // transposed batch stride
    const long long shVT = (long long)DH_ * S_; // transposed head stride
    dim3 gAV(1, 8, 32);
    gemm_mma_k<64, 0><<<gAV, 256, SM64>>>(
        bp + O_PH, bp + O_PL, bp + O_VTH, bp + O_VTL,
        S_, S_, S_, D_, sbF, shF, sbVT, shVT, sbH, shH, 1.f,
        out, x, nullptr, nullptr, nullptr, nullptr, nullptr, 0, 0);
    gemm_mma_k<64, 1><<<gAV, 256, SM64>>>(
        bp + O_G, bp + O_P2, bp + O_VVVT, bp + O_VVT,
        S_, S_, S_, D_, sbF, shF, sbVT, shVT, sbH, shH, 1.f,
        out + SZ_TOK, nullptr, nullptr, nullptr, nullptr, nullptr, nullptr, 0, 0);
}

// round 5
// speedup vs baseline: 1.9126x; 1.0032x over previous
#include <cuda_runtime.h>
#include <cuda_bf16.h>
#include <cuda_fp16.h>
#include <cstdint>

typedef __nv_bfloat16 bf16;

// ---------------------------------------------------------------------------
// AttentionHeadVDP: B=2, S=1024, D=1024, H=16, dh=64, fp32
// R5: fp16 operands, fused scores+softmax kernel, 2-term AV-mu
// ---------------------------------------------------------------------------
#define B_  2
#define S_  1024
#define D_  1024
#define H_  16
#define DH_ 64

static const long long SZ_TOK = 2097152LL;   // B*S*D
static const long long SZ_W   = 1048576LL;   // D*D
static const long long SZ_ATT = 33554432LL;  // B*H*S*S

// ---- half pool offsets (elements) ----
#define HXH   (0LL  * SZ_TOK)
#define HXL   (1LL  * SZ_TOK)
#define HX2   (2LL  * SZ_TOK)
#define HVX   (3LL  * SZ_TOK)
#define HQH   (4LL  * SZ_TOK)
#define HQL   (5LL  * SZ_TOK)
#define HQ2   (6LL  * SZ_TOK)
#define HKH   (7LL  * SZ_TOK)
#define HKL   (8LL  * SZ_TOK)
#define HVT   (9LL  * SZ_TOK)
#define HVQ   (10LL * SZ_TOK)
#define HVK   (11LL * SZ_TOK)
#define HVKK  (12LL * SZ_TOK)
#define HW0   (13LL * SZ_TOK)
#define WQMH  (HW0 + 0LL  * SZ_W)
#define WQML  (HW0 + 1LL  * SZ_W)
#define WQV   (HW0 + 2LL  * SZ_W)
#define WQP   (HW0 + 3LL  * SZ_W)
#define WKMH  (HW0 + 4LL  * SZ_W)
#define WKML  (HW0 + 5LL  * SZ_W)
#define WKV   (HW0 + 6LL  * SZ_W)
#define WKP   (HW0 + 7LL  * SZ_W)
#define WVMH  (HW0 + 8LL  * SZ_W)
#define WVML  (HW0 + 9LL  * SZ_W)
#define WVV   (HW0 + 10LL * SZ_W)
#define WVP   (HW0 + 11LL * SZ_W)
#define HPH   (HW0 + 12LL * SZ_W)
#define HPL   (HPH + SZ_ATT)
#define H_TOTAL (HPL + SZ_ATT)

// ---- bf16 pool offsets ----
#define BP2   (0LL)
#define BG    (1LL * SZ_ATT)
#define BVVT  (2LL * SZ_ATT)
#define BVVVT (2LL * SZ_ATT + SZ_TOK)
#define B_TOTAL (2LL * SZ_ATT + 2LL * SZ_TOK)

__device__ half  g_h[H_TOTAL];
__device__ bf16  g_b[B_TOTAL];
__device__ float g_kf[SZ_TOK];
__device__ float g_vf[SZ_TOK];

// ---------------------------------------------------------------------------
// PTX helpers
// ---------------------------------------------------------------------------
__device__ __forceinline__ uint32_t smem_to_u32(const void* p) {
    uint32_t a;
    asm("{ .reg .u64 t; cvta.to.shared.u64 t, %1; cvt.u32.u64 %0, t; }" : "=r"(a) : "l"(p));
    return a;
}
__device__ __forceinline__ void cp16(uint32_t s, const void* g) {
    asm volatile("cp.async.cg.shared.global [%0], [%1], 16;" :: "r"(s), "l"(g) : "memory");
}
#define CP_COMMIT() asm volatile("cp.async.commit_group;" ::: "memory")
#define CP_WAIT(n)  asm volatile("cp.async.wait_group %0;" :: "n"(n) : "memory")

__device__ __forceinline__ void ldsm4(uint32_t* r, uint32_t addr) {
    asm volatile("ldmatrix.sync.aligned.m8n8.x4.shared.b16 {%0,%1,%2,%3}, [%4];"
        : "=r"(r[0]), "=r"(r[1]), "=r"(r[2]), "=r"(r[3]) : "r"(addr));
}
__device__ __forceinline__ void mma_h(float* c, const uint32_t* a, const uint32_t* b) {
    asm volatile(
        "mma.sync.aligned.m16n8k16.row.col.f32.f16.f16.f32 "
        "{%0,%1,%2,%3}, {%4,%5,%6,%7}, {%8,%9}, {%0,%1,%2,%3};"
        : "+f"(c[0]), "+f"(c[1]), "+f"(c[2]), "+f"(c[3])
        : "r"(a[0]), "r"(a[1]), "r"(a[2]), "r"(a[3]), "r"(b[0]), "r"(b[1]));
}
__device__ __forceinline__ void mma_b(float* c, const uint32_t* a, const uint32_t* b) {
    asm volatile(
        "mma.sync.aligned.m16n8k16.row.col.f32.bf16.bf16.f32 "
        "{%0,%1,%2,%3}, {%4,%5,%6,%7}, {%8,%9}, {%0,%1,%2,%3};"
        : "+f"(c[0]), "+f"(c[1]), "+f"(c[2]), "+f"(c[3])
        : "r"(a[0]), "r"(a[1]), "r"(a[2]), "r"(a[3]), "r"(b[0]), "r"(b[1]));
}

__device__ __forceinline__ void hsplit(float a, half* h, half* l) {
    half hh = __float2half(a);
    *h = hh; *l = __float2half(a - __half2float(hh));
}
__device__ __forceinline__ void st1(half* p, float v) { *p = __float2half(v); }
__device__ __forceinline__ void st1(bf16* p, float v) { *p = __float2bfloat16(v); }
__device__ __forceinline__ void stsp(half* h, half* l, float v) { hsplit(v, h, l); }
__device__ __forceinline__ void stsp(bf16* h, bf16* l, float v) {
    bf16 hh = __float2bfloat16(v);
    *h = hh; *l = __float2bfloat16(v - __bfloat162float(hh));
}

// ---------------------------------------------------------------------------
// one fused conversion kernel (launch #1)
// ---------------------------------------------------------------------------
__global__ void conv_all_k(const float* __restrict__ x, const float* __restrict__ vx,
                           const float* __restrict__ wqm, const float* __restrict__ wqv,
                           const float* __restrict__ wkm, const float* __restrict__ wkv,
                           const float* __restrict__ wvm, const float* __restrict__ wvv,
                           half* __restrict__ hp) {
    const int i = blockIdx.x * 256 + threadIdx.x;
    if (i < (int)SZ_TOK) {
        float a = x[i];
        hsplit(a, hp + HXH + i, hp + HXL + i);
        hp[HX2 + i] = __float2half(a * a);
        hp[HVX + i] = __float2half(vx[i]);
    }
    if (i < (int)SZ_W) {
        float m, v;
        m = wqm[i]; v = wqv[i];
        hsplit(m, hp + WQMH + i, hp + WQML + i);
        hp[WQV + i] = __float2half(v);
        hp[WQP + i] = __float2half(fmaf(m, m, v));
        m = wkm[i]; v = wkv[i];
        hsplit(m, hp + WKMH + i, hp + WKML + i);
        hp[WKV + i] = __float2half(v);
        hp[WKP + i] = __float2half(fmaf(m, m, v));
        m = wvm[i]; v = wvv[i];
        hsplit(m, hp + WVMH + i, hp + WVML + i);
        hp[WVV + i] = __float2half(v);
        hp[WVP + i] = __float2half(fmaf(m, m, v));
    }
}

// ---------------------------------------------------------------------------
// warp-MMA GEMM.  MODE 0: A0B0+A1B0+A0B1 | 1: A0B0+A1B1 | 2: A0B0+A1B0
// F16: operand mma type. OT: 16-bit output type.
// ---------------------------------------------------------------------------
template<int BN, int MODE, bool F16, typename OT>
__global__ __launch_bounds__(256)
void gemm_mma_k(const uint16_t* __restrict__ A0, const uint16_t* __restrict__ A1,
                const uint16_t* __restrict__ B0, const uint16_t* __restrict__ B1,
                int K, int lda, int ldb, int ldc,
                long long sbA, long long shA, long long sbB, long long shB,
                long long sbC, long long shC,
                float alpha,
                float* __restrict__ cf, const float* __restrict__ addp,
                OT* __restrict__ ch, OT* __restrict__ cl, OT* __restrict__ cs,
                const float* __restrict__ auxf, OT* __restrict__ ds, int auxmode,
                int transC)
{
    constexpr int BM = 128, BK = 32, SK = 40;
    constexpr int NMATB = (MODE == 2) ? 1 : 2;
    constexpr int WARPS_N = (BN == 128) ? 4 : 2;
    constexpr int WARPS_M = 8 / WARPS_N;
    constexpr int WM = BM / WARPS_M, WN = BN / WARPS_N;
    constexpr int MT = WM / 16, NT = WN / 8;
    constexpr int ATILE = BM * SK * 2;
    constexpr int BTILE = BN * SK * 2;
    constexpr int BUFB  = 2 * ATILE + NMATB * BTILE;

    extern __shared__ char smem[];
    const uint32_t s32 = smem_to_u32(smem);
    const int tid = threadIdx.x;
    const int wid = tid >> 5, lane = tid & 31;
    const int wm = wid / WARPS_N, wn = wid % WARPS_N;

    const int bz = blockIdx.z, bb = bz >> 4, hh = bz & 15;
    const long long offA = (long long)bb * sbA + (long long)hh * shA;
    const long long offB = (long long)bb * sbB + (long long)hh * shB;
    const long long offC = (long long)bb * sbC + (long long)hh * shC;
    const int m0 = blockIdx.y * BM;
    const int n0 = blockIdx.x * BN;

    auto loadbuf = [&](int kc, int buf) {
        const int k0 = kc * BK;
        const uint32_t b32 = s32 + buf * BUFB;
#pragma unroll
        for (int i = 0; i < BM * 4 / 256; i++) {
            const int c = tid + i * 256;
            const int row = c >> 2, seg = c & 3;
            const long long go = offA + (long long)(m0 + row) * lda + k0 + seg * 8;
            const uint32_t so = (uint32_t)(row * SK + seg * 8) * 2;
            cp16(b32 + so, A0 + go);
            cp16(b32 + ATILE + so, A1 + go);
        }
#pragma unroll
        for (int i = 0; i < BN * 4 / 256; i++) {
            const int c = tid + i * 256;
            const int row = c >> 2, seg = c & 3;
            const long long go = offB + (long long)(n0 + row) * ldb + k0 + seg * 8;
            const uint32_t so = (uint32_t)(row * SK + seg * 8) * 2;
            cp16(b32 + 2 * ATILE + so, B0 + go);
            if (NMATB == 2) cp16(b32 + 2 * ATILE + BTILE + so, B1 + go);
        }
        CP_COMMIT();
    };

    float acc[MT][NT][4];
#pragma unroll
    for (int i = 0; i < MT; i++)
#pragma unroll
        for (int j = 0; j < NT; j++)
#pragma unroll
            for (int r = 0; r < 4; r++) acc[i][j][r] = 0.f;

    const int NKC = K / BK;
    loadbuf(0, 0);

    for (int kc = 0; kc < NKC; kc++) {
        const int buf = kc & 1;
        if (kc + 1 < NKC) { loadbuf(kc + 1, buf ^ 1); CP_WAIT(1); }
        else              { CP_WAIT(0); }
        __syncthreads();

        const uint32_t b32 = s32 + buf * BUFB;
#pragma unroll
        for (int kh = 0; kh < 2; kh++) {
            const int kcol = kh * 16 + (lane >> 4) * 8;
            uint32_t afr[2][MT][4];
            uint32_t bfr[NMATB][NT][2];
#pragma unroll
            for (int mat = 0; mat < 2; mat++)
#pragma unroll
                for (int mt = 0; mt < MT; mt++) {
                    const int row = wm * WM + mt * 16 + (lane & 15);
                    ldsm4(afr[mat][mt], b32 + mat * ATILE + (uint32_t)(row * SK + kcol) * 2);
                }
#pragma unroll
            for (int mat = 0; mat < NMATB; mat++)
#pragma unroll
                for (int nt2 = 0; nt2 < NT / 2; nt2++) {
                    const int row = wn * WN + nt2 * 16 + (lane & 15);
                    uint32_t r[4];
                    ldsm4(r, b32 + 2 * ATILE + mat * BTILE + (uint32_t)(row * SK + kcol) * 2);
                    bfr[mat][2 * nt2][0]     = r[0]; bfr[mat][2 * nt2][1]     = r[2];
                    bfr[mat][2 * nt2 + 1][0] = r[1]; bfr[mat][2 * nt2 + 1][1] = r[3];
                }

#define DO_MMA(AM, BM_) \
            for (int mt = 0; mt < MT; mt++) \
                for (int nt = 0; nt < NT; nt++) { \
                    if (F16) mma_h(acc[mt][nt], afr[AM][mt], bfr[BM_][nt]); \
                    else     mma_b(acc[mt][nt], afr[AM][mt], bfr[BM_][nt]); \
                }
            DO_MMA(0, 0)
            if (MODE == 0) { DO_MMA(1, 0) DO_MMA(0, 1) }
            else if (MODE == 1) { DO_MMA(1, 1) }
            else { DO_MMA(1, 0) }
#undef DO_MMA
        }
        __syncthreads();
    }

    // ---- epilogue ----
#pragma unroll
    for (int mt = 0; mt < MT; mt++) {
#pragma unroll
        for (int nt = 0; nt < NT; nt++) {
#pragma unroll
            for (int rp = 0; rp < 2; rp++) {
                const int m = m0 + wm * WM + mt * 16 + (lane >> 2) + rp * 8;
                const int nbase = n0 + wn * WN + nt * 8 + (lane & 3) * 2;
#pragma unroll
                for (int cc = 0; cc < 2; cc++) {
                    const int n = nbase + cc;
                    float val = alpha * acc[mt][nt][rp * 2 + cc];
                    const long long idx = offC + (long long)m * ldc + n;
                    if (addp) val += addp[idx];
                    if (cf) cf[idx] = val;
                    const long long bidx = transC
                        ? ((long long)(m >> 10) * ((long long)D_ * S_) + (long long)n * S_ + (m & (S_ - 1)))
                        : idx;
                    if (ch) stsp(ch + bidx, cl + bidx, val);
                    if (cs) st1(cs + bidx, val);
                    if (auxmode) {
                        const float t = (auxmode == 1) ? val * val
                                                       : fmaf(auxf[idx], auxf[idx], val);
                        st1(ds + bidx, t);
                    }
                }
            }
        }
    }
}

// ---------------------------------------------------------------------------
// fused scores + softmax-VDP kernel.
// CTA: 16 q-rows x full 1024 cols for one (b,h). 8 warps, each owns a 16-col
// strip per 128-col chunk. Accumulates S (3 terms) and VS (2 terms) in regs,
// does row softmax, writes ph/pl (fp16), p2/g (bf16) directly.
// ---------------------------------------------------------------------------
#define SKQ 72
__global__ __launch_bounds__(256)
void scores_k(const uint16_t* __restrict__ qh, const uint16_t* __restrict__ ql,
              const uint16_t* __restrict__ vq, const uint16_t* __restrict__ q2,
              const uint16_t* __restrict__ kh, const uint16_t* __restrict__ kl,
              const uint16_t* __restrict__ vkk, const uint16_t* __restrict__ vk,
              half* __restrict__ ph, half* __restrict__ pl,
              bf16* __restrict__ p2, bf16* __restrict__ g)
{
    constexpr int QT = 16 * SKQ * 2;     // 2304 B per q tile
    constexpr int KT = 128 * SKQ * 2;    // 18432 B per K tile
    constexpr int QB = 4 * QT;           // 9216
    constexpr int KBUF = 4 * KT;         // 73728
    constexpr int RB = QB + 2 * KBUF;    // 156672

    extern __shared__ char smem[];
    const uint32_t s32 = smem_to_u32(smem);
    const int tid = threadIdx.x, wid = tid >> 5, lane = tid & 31;
    const int bh = blockIdx.y, bb = bh >> 4, hh = bh & 15;
    const int m0 = blockIdx.x * 16;
    const long long tokOff = (long long)bb * S_ * D_ + (long long)hh * DH_;
    const long long attOff = (long long)bh * ((long long)S_ * S_);

    // q tiles (4 arrays x 16 x 64)
#pragma unroll
    for (int i = 0; i < 2; i++) {
        const int c = tid + i * 256;
        const int arr = c >> 7, r = (c >> 3) & 15, seg = c & 7;
        const uint16_t* src = (arr == 0) ? qh : (arr == 1) ? ql : (arr == 2) ? vq : q2;
        cp16(s32 + arr * QT + (uint32_t)(r * SKQ + seg * 8) * 2,
             src + tokOff + (long long)(m0 + r) * D_ + seg * 8);
    }
    CP_COMMIT();

    auto loadK = [&](int c0, int buf) {
        const uint32_t kb = s32 + QB + buf * KBUF;
#pragma unroll
        for (int i = 0; i < 16; i++) {
            const int c = tid + i * 256;
            const int arr = c >> 10, rr = (c >> 3) & 127, seg = c & 7;
            const uint16_t* src = (arr == 0) ? kh : (arr == 1) ? kl : (arr == 2) ? vkk : vk;
            cp16(kb + arr * KT + (uint32_t)(rr * SKQ + seg * 8) * 2,
                 src + tokOff + (long long)(c0 * 128 + rr) * D_ + seg * 8);
        }
        CP_COMMIT();
    };

    float accS[8][2][4], accVS[8][2][4];
#pragma unroll
    for (int c = 0; c < 8; c++)
#pragma unroll
        for (int nt = 0; nt < 2; nt++)
#pragma unroll
            for (int r = 0; r < 4; r++) { accS[c][nt][r] = 0.f; accVS[c][nt][r] = 0.f; }

    loadK(0, 0);
#pragma unroll
    for (int c0 = 0; c0 < 8; c0++) {
        const int buf = c0 & 1;
        if (c0 + 1 < 8) { loadK(c0 + 1, buf ^ 1); CP_WAIT(1); }
        else            { CP_WAIT(0); }
        __syncthreads();
        const uint32_t kb = s32 + QB + buf * KBUF;
#pragma unroll
        for (int ks = 0; ks < 4; ks++) {
            const int kcol = ks * 16 + (lane >> 4) * 8;
            uint32_t af[4][4];
#pragma unroll
            for (int m = 0; m < 4; m++)
                ldsm4(af[m], s32 + m * QT + (uint32_t)((lane & 15) * SKQ + kcol) * 2);
            uint32_t bfr[4][2][2];
#pragma unroll
            for (int m = 0; m < 4; m++) {
                uint32_t r[4];
                ldsm4(r, kb + m * KT + (uint32_t)((wid * 16 + (lane & 15)) * SKQ + kcol) * 2);
                bfr[m][0][0] = r[0]; bfr[m][0][1] = r[2];
                bfr[m][1][0] = r[1]; bfr[m][1][1] = r[3];
            }
#pragma unroll
            for (int nt = 0; nt < 2; nt++) {
                mma_h(accS[c0][nt],  af[0], bfr[0][nt]);   // qh.kh
                mma_h(accS[c0][nt],  af[1], bfr[0][nt]);   // ql.kh
                mma_h(accS[c0][nt],  af[0], bfr[1][nt]);   // qh.kl
                mma_h(accVS[c0][nt], af[2], bfr[2][nt]);   // vq.vkk
                mma_h(accVS[c0][nt], af[3], bfr[3][nt]);   // q2.vk
            }
        }
        __syncthreads();
    }

    // ---- softmax over rows (16 rows, 1024 cols) ----
    float* red = (float*)(smem + RB);  // [16][8]
    const int r0 = lane >> 2;
    const float sscale = 1.0f / 32.0f;
    float mx[2] = {-1e30f, -1e30f};
#pragma unroll
    for (int c = 0; c < 8; c++)
#pragma unroll
        for (int nt = 0; nt < 2; nt++)
#pragma unroll
            for (int rp = 0; rp < 2; rp++) {
                mx[rp] = fmaxf(mx[rp], fmaxf(accS[c][nt][rp * 2], accS[c][nt][rp * 2 + 1]));
            }
    mx[0] *= sscale; mx[1] *= sscale;
#pragma unroll
    for (int d = 1; d <= 2; d <<= 1) {
        mx[0] = fmaxf(mx[0], __shfl_xor_sync(0xffffffff, mx[0], d));
        mx[1] = fmaxf(mx[1], __shfl_xor_sync(0xffffffff, mx[1], d));
    }
    if ((lane & 3) == 0) {
        red[r0 * 8 + wid] = mx[0];
        red[(r0 + 8) * 8 + wid] = mx[1];
    }
    __syncthreads();
    float rmx[2];
#pragma unroll
    for (int rp = 0; rp < 2; rp++) {
        float v = -1e30f;
#pragma unroll
        for (int w = 0; w < 8; w++) v = fmaxf(v, red[(r0 + rp * 8) * 8 + w]);
        rmx[rp] = v;
    }
    __syncthreads();
    float sm[2] = {0.f, 0.f};
#pragma unroll
    for (int c = 0; c < 8; c++)
#pragma unroll
        for (int nt = 0; nt < 2; nt++)
#pragma unroll
            for (int rp = 0; rp < 2; rp++)
#pragma unroll
                for (int cc = 0; cc < 2; cc++) {
                    float e = __expf(accS[c][nt][rp * 2 + cc] * sscale - rmx[rp]);
                    accS[c][nt][rp * 2 + cc] = e;
                    sm[rp] += e;
                }
#pragma unroll
    for (int d = 1; d <= 2; d <<= 1) {
        sm[0] += __shfl_xor_sync(0xffffffff, sm[0], d);
        sm[1] += __shfl_xor_sync(0xffffffff, sm[1], d);
    }
    if ((lane & 3) == 0) {
        red[r0 * 8 + wid] = sm[0];
        red[(r0 + 8) * 8 + wid] = sm[1];
    }
    __syncthreads();
    float inv[2];
#pragma unroll
    for (int rp = 0; rp < 2; rp++) {
        float v = 0.f;
#pragma unroll
        for (int w = 0; w < 8; w++) v += red[(r0 + rp * 8) * 8 + w];
        inv[rp] = 1.0f / v;
    }

    // ---- outputs ----
    const float vscale = 1.0f / 1024.0f;
#pragma unroll
    for (int c = 0; c < 8; c++)
#pragma unroll
        for (int nt = 0; nt < 2; nt++)
#pragma unroll
            for (int rp = 0; rp < 2; rp++)
#pragma unroll
                for (int cc = 0; cc < 2; cc++) {
                    const int col = c * 128 + wid * 16 + nt * 8 + (lane & 3) * 2 + cc;
                    const int row = m0 + r0 + rp * 8;
                    const long long idx = attOff + (long long)row * S_ + col;
                    const float p = accS[c][nt][rp * 2 + cc] * inv[rp];
                    half hp_ = __float2half(p);
                    ph[idx] = hp_;
                    pl[idx] = __float2half(p - __half2float(hp_));
                    const float vs = accVS[c][nt][rp * 2 + cc] * vscale;
                    const float pm = p * (1.0f - p);
                    p2[idx] = __float2bfloat16(p * p);
                    g[idx]  = __float2bfloat16(pm * pm * vs);
                }
}

// ---------------------------------------------------------------------------
// host orchestration
// ---------------------------------------------------------------------------
extern "C" void kernel_launch(void* const* d_in, const int* in_sizes, int n_in,
                              void* d_out, int out_size)
{
    (void)in_sizes; (void)n_in; (void)out_size;
    const float* x      = (const float*)d_in[0];
    const float* var_x  = (const float*)d_in[1];
    const float* wq_mu  = (const float*)d_in[2];
    const float* wq_var = (const float*)d_in[3];
    const float* wk_mu  = (const float*)d_in[4];
    const float* wk_var = (const float*)d_in[5];
    const float* wv_mu  = (const float*)d_in[6];
    const float* wv_var = (const float*)d_in[7];
    float* out = (float*)d_out;

    half* hp = nullptr;  cudaGetSymbolAddress((void**)&hp, g_h);
    bf16* bp = nullptr;  cudaGetSymbolAddress((void**)&bp, g_b);
    float* kf = nullptr; cudaGetSymbolAddress((void**)&kf, g_kf);
    float* vf = nullptr; cudaGetSymbolAddress((void**)&vf, g_vf);

    const int SM128 = 2 * (2 * 10240 + 2 * 10240);  // 81920
    const int SM64_1 = 2 * (2 * 10240 + 2 * 5120);  // 61440
    const int SM64_2 = 2 * (2 * 10240 + 1 * 5120);  // 51200
    const int SMSC = 9216 + 2 * 73728 + 512;        // 157184
    cudaFuncSetAttribute(gemm_mma_k<128, 0, true, half>,  cudaFuncAttributeMaxDynamicSharedMemorySize, SM128);
    cudaFuncSetAttribute(gemm_mma_k<128, 1, true, half>,  cudaFuncAttributeMaxDynamicSharedMemorySize, SM128);
    cudaFuncSetAttribute(gemm_mma_k<128, 1, true, bf16>,  cudaFuncAttributeMaxDynamicSharedMemorySize, SM128);
    cudaFuncSetAttribute(gemm_mma_k<64, 2, true, half>,   cudaFuncAttributeMaxDynamicSharedMemorySize, SM64_2);
    cudaFuncSetAttribute(gemm_mma_k<64, 1, false, bf16>,  cudaFuncAttributeMaxDynamicSharedMemorySize, SM64_1);
    cudaFuncSetAttribute(scores_k, cudaFuncAttributeMaxDynamicSharedMemorySize, SMSC);

    // 1) conversions
    conv_all_k<<<(int)(SZ_TOK / 256), 256>>>(x, var_x, wq_mu, wq_var, wk_mu, wk_var,
                                             wv_mu, wv_var, hp);

    const uint16_t* u = (const uint16_t*)hp;
    dim3 gP(8, 16, 1);
    // 2) q mu: split qh/ql + q2 = val^2
    gemm_mma_k<128, 0, true, half><<<gP, 256, SM128>>>(
        u + HXH, u + HXL, u + WQMH, u + WQML,
        D_, D_, D_, D_, 0, 0, 0, 0, 0, 0, 1.f,
        nullptr, nullptr, hp + HQH, hp + HQL, nullptr,
        nullptr, hp + HQ2, 1, 0);
    // 3) k mu: split kh/kl + fp32 kf
    gemm_mma_k<128, 0, true, half><<<gP, 256, SM128>>>(
        u + HXH, u + HXL, u + WKMH, u + WKML,
        D_, D_, D_, D_, 0, 0, 0, 0, 0, 0, 1.f,
        kf, nullptr, hp + HKH, hp + HKL, nullptr,
        nullptr, nullptr, 0, 0);
    // 4) v mu: fp32 vf + single fp16 transposed vt
    gemm_mma_k<128, 0, true, half><<<gP, 256, SM128>>>(
        u + HXH, u + HXL, u + WVMH, u + WVML,
        D_, D_, D_, D_, 0, 0, 0, 0, 0, 0, 1.f,
        vf, nullptr, nullptr, nullptr, hp + HVT,
        nullptr, nullptr, 0, 1);
    // 5) vq = vx@wqp^T + x2@wqv^T
    gemm_mma_k<128, 1, true, half><<<gP, 256, SM128>>>(
        u + HVX, u + HX2, u + WQP, u + WQV,
        D_, D_, D_, D_, 0, 0, 0, 0, 0, 0, 1.f,
        nullptr, nullptr, nullptr, nullptr, hp + HVQ,
        nullptr, nullptr, 0, 0);
    // 6) vk ; vkk = vk + kf^2
    gemm_mma_k<128, 1, true, half><<<gP, 256, SM128>>>(
        u + HVX, u + HX2, u + WKP, u + WKV,
        D_, D_, D_, D_, 0, 0, 0, 0, 0, 0, 1.f,
        nullptr, nullptr, nullptr, nullptr, hp + HVK,
        kf, hp + HVKK, 2, 0);
    // 7) vv (transposed, bf16) ; vvv = vv + vf^2 (transposed, bf16)
    gemm_mma_k<128, 1, true, bf16><<<gP, 256, SM128>>>(
        u + HVX, u + HX2, u + WVP, u + WVV,
        D_, D_, D_, D_, 0, 0, 0, 0, 0, 0, 1.f,
        nullptr, nullptr, nullptr, nullptr, bp + BVVT,
        vf, bp + BVVVT, 2, 1);

    // 8) fused scores + softmax
    scores_k<<<dim3(64, 32), 256, SMSC>>>(
        u + HQH, u + HQL, u + HVQ, u + HQ2,
        u + HKH, u + HKL, u + HVKK, u + HVK,
        hp + HPH, hp + HPL, bp + BP2, bp + BG);

    // 9/10) AV
    const long long sbF = (long long)H_ * S_ * S_, shF = (long long)S_ * S_;
    const long long sbH = (long long)S_ * D_;
    const long long sbVT = (long long)D_ * S_, shVT = (long long)DH_ * S_;
    dim3 gAV(1, 8, 32);
    gemm_mma_k<64, 2, true, half><<<gAV, 256, SM64_2>>>(
        u + HPH, u + HPL, u + HVT, nullptr,
        S_, S_, S_, D_, sbF, shF, sbVT, shVT, sbH, DH_, 1.f,
        out, x, nullptr, nullptr, nullptr, nullptr, nullptr, 0, 0);
    gemm_mma_k<64, 1, false, bf16><<<gAV, 256, SM64_1>>>(
        (const uint16_t*)(bp + BG), (const uint16_t*)(bp + BP2),
        (const uint16_t*)(bp + BVVVT), (const uint16_t*)(bp + BVVT),
        S_, S_, S_, D_, sbF, shF, sbVT, shVT, sbH, DH_, 1.f,
        out + SZ_TOK, nullptr, nullptr, nullptr, nullptr, nullptr, nullptr, 0, 0);
}

// round 6
// speedup vs baseline: 2.8432x; 1.4866x over previous
#include <cuda_runtime.h>
#include <cuda_bf16.h>
#include <cuda_fp16.h>
#include <cstdint>

typedef __nv_bfloat16 bf16;

#define B_  2
#define S_  1024
#define D_  1024
#define H_  16
#define DH_ 64

static const long long SZ_TOK = 2097152LL;
static const long long SZ_W   = 1048576LL;
static const long long SZ_ATT = 33554432LL;

// ---- half pool offsets (elements) ----
#define HXH   (0LL  * SZ_TOK)
#define HXL   (1LL  * SZ_TOK)
#define HX2   (2LL  * SZ_TOK)
#define HVX   (3LL  * SZ_TOK)
#define HQH   (4LL  * SZ_TOK)
#define HQL   (5LL  * SZ_TOK)
#define HQ2   (6LL  * SZ_TOK)
#define HKH   (7LL  * SZ_TOK)
#define HKL   (8LL  * SZ_TOK)
#define HVT   (9LL  * SZ_TOK)
#define HVQ   (10LL * SZ_TOK)
#define HVK   (11LL * SZ_TOK)
#define HVKK  (12LL * SZ_TOK)
#define HW0   (13LL * SZ_TOK)
#define WQMH  (HW0 + 0LL  * SZ_W)
#define WQML  (HW0 + 1LL  * SZ_W)
#define WQV   (HW0 + 2LL  * SZ_W)
#define WQP   (HW0 + 3LL  * SZ_W)
#define WKMH  (HW0 + 4LL  * SZ_W)
#define WKML  (HW0 + 5LL  * SZ_W)
#define WKV   (HW0 + 6LL  * SZ_W)
#define WKP   (HW0 + 7LL  * SZ_W)
#define WVMH  (HW0 + 8LL  * SZ_W)
#define WVML  (HW0 + 9LL  * SZ_W)
#define WVV   (HW0 + 10LL * SZ_W)
#define WVP   (HW0 + 11LL * SZ_W)
#define HPH   (HW0 + 12LL * SZ_W)
#define HPL   (HPH + SZ_ATT)
#define H_TOTAL (HPL + SZ_ATT)

// ---- bf16 pool offsets ----
#define BP2   (0LL)
#define BG    (1LL * SZ_ATT)
#define BVVT  (2LL * SZ_ATT)
#define BVVVT (2LL * SZ_ATT + SZ_TOK)
#define B_TOTAL (2LL * SZ_ATT + 2LL * SZ_TOK)

__device__ half  g_h[H_TOTAL];
__device__ bf16  g_b[B_TOTAL];
__device__ float g_kf[SZ_TOK];
__device__ float g_vf[SZ_TOK];

// ---------------------------------------------------------------------------
__device__ __forceinline__ uint32_t smem_to_u32(const void* p) {
    uint32_t a;
    asm("{ .reg .u64 t; cvta.to.shared.u64 t, %1; cvt.u32.u64 %0, t; }" : "=r"(a) : "l"(p));
    return a;
}
__device__ __forceinline__ void cp16(uint32_t s, const void* g) {
    asm volatile("cp.async.cg.shared.global [%0], [%1], 16;" :: "r"(s), "l"(g) : "memory");
}
#define CP_COMMIT() asm volatile("cp.async.commit_group;" ::: "memory")
#define CP_WAIT(n)  asm volatile("cp.async.wait_group %0;" :: "n"(n) : "memory")

__device__ __forceinline__ void ldsm4(uint32_t* r, uint32_t addr) {
    asm volatile("ldmatrix.sync.aligned.m8n8.x4.shared.b16 {%0,%1,%2,%3}, [%4];"
        : "=r"(r[0]), "=r"(r[1]), "=r"(r[2]), "=r"(r[3]) : "r"(addr));
}
__device__ __forceinline__ void mma_h(float* c, const uint32_t* a, const uint32_t* b) {
    asm volatile(
        "mma.sync.aligned.m16n8k16.row.col.f32.f16.f16.f32 "
        "{%0,%1,%2,%3}, {%4,%5,%6,%7}, {%8,%9}, {%0,%1,%2,%3};"
        : "+f"(c[0]), "+f"(c[1]), "+f"(c[2]), "+f"(c[3])
        : "r"(a[0]), "r"(a[1]), "r"(a[2]), "r"(a[3]), "r"(b[0]), "r"(b[1]));
}
__device__ __forceinline__ void mma_b(float* c, const uint32_t* a, const uint32_t* b) {
    asm volatile(
        "mma.sync.aligned.m16n8k16.row.col.f32.bf16.bf16.f32 "
        "{%0,%1,%2,%3}, {%4,%5,%6,%7}, {%8,%9}, {%0,%1,%2,%3};"
        : "+f"(c[0]), "+f"(c[1]), "+f"(c[2]), "+f"(c[3])
        : "r"(a[0]), "r"(a[1]), "r"(a[2]), "r"(a[3]), "r"(b[0]), "r"(b[1]));
}
__device__ __forceinline__ void hsplit(float a, half* h, half* l) {
    half hh = __float2half(a);
    *h = hh; *l = __float2half(a - __half2float(hh));
}
__device__ __forceinline__ void st1(half* p, float v) { *p = __float2half(v); }
__device__ __forceinline__ void st1(bf16* p, float v) { *p = __float2bfloat16(v); }
__device__ __forceinline__ void stsp(half* h, half* l, float v) { hsplit(v, h, l); }
__device__ __forceinline__ void stsp(bf16* h, bf16* l, float v) {
    bf16 hh = __float2bfloat16(v);
    *h = hh; *l = __float2bfloat16(v - __bfloat162float(hh));
}

// ---------------------------------------------------------------------------
__global__ void conv_all_k(const float* __restrict__ x, const float* __restrict__ vx,
                           const float* __restrict__ wqm, const float* __restrict__ wqv,
                           const float* __restrict__ wkm, const float* __restrict__ wkv,
                           const float* __restrict__ wvm, const float* __restrict__ wvv,
                           half* __restrict__ hp) {
    const int i = blockIdx.x * 256 + threadIdx.x;
    if (i < (int)SZ_TOK) {
        float a = x[i];
        hsplit(a, hp + HXH + i, hp + HXL + i);
        hp[HX2 + i] = __float2half(a * a);
        hp[HVX + i] = __float2half(vx[i]);
    }
    if (i < (int)SZ_W) {
        float m, v;
        m = wqm[i]; v = wqv[i];
        hsplit(m, hp + WQMH + i, hp + WQML + i);
        hp[WQV + i] = __float2half(v);
        hp[WQP + i] = __float2half(fmaf(m, m, v));
        m = wkm[i]; v = wkv[i];
        hsplit(m, hp + WKMH + i, hp + WKML + i);
        hp[WKV + i] = __float2half(v);
        hp[WKP + i] = __float2half(fmaf(m, m, v));
        m = wvm[i]; v = wvv[i];
        hsplit(m, hp + WVMH + i, hp + WVML + i);
        hp[WVV + i] = __float2half(v);
        hp[WVP + i] = __float2half(fmaf(m, m, v));
    }
}

// ---------------------------------------------------------------------------
// GEMM body (device function).  MODE 0: A0B0+A1B0+A0B1 | 1: A0B0+A1B1 | 2: A0B0+A1B0
// ---------------------------------------------------------------------------
template<int BN, int MODE, bool F16, typename OT>
__device__ __forceinline__
void gemm_body(const uint16_t* __restrict__ A0, const uint16_t* __restrict__ A1,
               const uint16_t* __restrict__ B0, const uint16_t* __restrict__ B1,
               int K, int lda, int ldb, int ldc,
               long long sbA, long long shA, long long sbB, long long shB,
               long long sbC, long long shC, int bz,
               float alpha,
               float* __restrict__ cf, const float* __restrict__ addp,
               OT* __restrict__ ch, OT* __restrict__ cl, OT* __restrict__ cs,
               const float* __restrict__ auxf, OT* __restrict__ ds, int auxmode,
               int transC)
{
    constexpr int BM = 128, BK = 32, SK = 40;
    constexpr int NMATB = (MODE == 2) ? 1 : 2;
    constexpr int WARPS_N = (BN == 128) ? 4 : 2;
    constexpr int WARPS_M = 8 / WARPS_N;
    constexpr int WM = BM / WARPS_M, WN = BN / WARPS_N;
    constexpr int MT = WM / 16, NT = WN / 8;
    constexpr int ATILE = BM * SK * 2;
    constexpr int BTILE = BN * SK * 2;
    constexpr int BUFB  = 2 * ATILE + NMATB * BTILE;

    extern __shared__ char smem[];
    const uint32_t s32 = smem_to_u32(smem);
    const int tid = threadIdx.x;
    const int wid = tid >> 5, lane = tid & 31;
    const int wm = wid / WARPS_N, wn = wid % WARPS_N;

    const int bb = bz >> 4, hh = bz & 15;
    const long long offA = (long long)bb * sbA + (long long)hh * shA;
    const long long offB = (long long)bb * sbB + (long long)hh * shB;
    const long long offC = (long long)bb * sbC + (long long)hh * shC;
    const int m0 = blockIdx.y * BM;
    const int n0 = blockIdx.x * BN;

    auto loadbuf = [&](int kc, int buf) {
        const int k0 = kc * BK;
        const uint32_t b32 = s32 + buf * BUFB;
#pragma unroll
        for (int i = 0; i < BM * 4 / 256; i++) {
            const int c = tid + i * 256;
            const int row = c >> 2, seg = c & 3;
            const long long go = offA + (long long)(m0 + row) * lda + k0 + seg * 8;
            const uint32_t so = (uint32_t)(row * SK + seg * 8) * 2;
            cp16(b32 + so, A0 + go);
            cp16(b32 + ATILE + so, A1 + go);
        }
#pragma unroll
        for (int i = 0; i < BN * 4 / 256; i++) {
            const int c = tid + i * 256;
            const int row = c >> 2, seg = c & 3;
            const long long go = offB + (long long)(n0 + row) * ldb + k0 + seg * 8;
            const uint32_t so = (uint32_t)(row * SK + seg * 8) * 2;
            cp16(b32 + 2 * ATILE + so, B0 + go);
            if (NMATB == 2) cp16(b32 + 2 * ATILE + BTILE + so, B1 + go);
        }
        CP_COMMIT();
    };

    float acc[MT][NT][4];
#pragma unroll
    for (int i = 0; i < MT; i++)
#pragma unroll
        for (int j = 0; j < NT; j++)
#pragma unroll
            for (int r = 0; r < 4; r++) acc[i][j][r] = 0.f;

    const int NKC = K / BK;
    loadbuf(0, 0);

    for (int kc = 0; kc < NKC; kc++) {
        const int buf = kc & 1;
        if (kc + 1 < NKC) { loadbuf(kc + 1, buf ^ 1); CP_WAIT(1); }
        else              { CP_WAIT(0); }
        __syncthreads();

        const uint32_t b32 = s32 + buf * BUFB;
#pragma unroll
        for (int kh = 0; kh < 2; kh++) {
            const int kcol = kh * 16 + (lane >> 4) * 8;
            uint32_t afr[2][MT][4];
            uint32_t bfr[NMATB][NT][2];
#pragma unroll
            for (int mat = 0; mat < 2; mat++)
#pragma unroll
                for (int mt = 0; mt < MT; mt++) {
                    const int row = wm * WM + mt * 16 + (lane & 15);
                    ldsm4(afr[mat][mt], b32 + mat * ATILE + (uint32_t)(row * SK + kcol) * 2);
                }
#pragma unroll
            for (int mat = 0; mat < NMATB; mat++)
#pragma unroll
                for (int nt2 = 0; nt2 < NT / 2; nt2++) {
                    const int row = wn * WN + nt2 * 16 + (lane & 15);
                    uint32_t r[4];
                    ldsm4(r, b32 + 2 * ATILE + mat * BTILE + (uint32_t)(row * SK + kcol) * 2);
                    bfr[mat][2 * nt2][0]     = r[0]; bfr[mat][2 * nt2][1]     = r[2];
                    bfr[mat][2 * nt2 + 1][0] = r[1]; bfr[mat][2 * nt2 + 1][1] = r[3];
                }

#define DO_MMA(AM, BM_) \
            for (int mt = 0; mt < MT; mt++) \
                for (int nt = 0; nt < NT; nt++) { \
                    if (F16) mma_h(acc[mt][nt], afr[AM][mt], bfr[BM_][nt]); \
                    else     mma_b(acc[mt][nt], afr[AM][mt], bfr[BM_][nt]); \
                }
            DO_MMA(0, 0)
            if (MODE == 0) { DO_MMA(1, 0) DO_MMA(0, 1) }
            else if (MODE == 1) { DO_MMA(1, 1) }
            else { DO_MMA(1, 0) }
#undef DO_MMA
        }
        __syncthreads();
    }

#pragma unroll
    for (int mt = 0; mt < MT; mt++) {
#pragma unroll
        for (int nt = 0; nt < NT; nt++) {
#pragma unroll
            for (int rp = 0; rp < 2; rp++) {
                const int m = m0 + wm * WM + mt * 16 + (lane >> 2) + rp * 8;
                const int nbase = n0 + wn * WN + nt * 8 + (lane & 3) * 2;
#pragma unroll
                for (int cc = 0; cc < 2; cc++) {
                    const int n = nbase + cc;
                    float val = alpha * acc[mt][nt][rp * 2 + cc];
                    const long long idx = offC + (long long)m * ldc + n;
                    if (addp) val += addp[idx];
                    if (cf) cf[idx] = val;
                    const long long bidx = transC
                        ? ((long long)(m >> 10) * ((long long)D_ * S_) + (long long)n * S_ + (m & (S_ - 1)))
                        : idx;
                    if (ch) stsp(ch + bidx, cl + bidx, val);
                    if (cs) st1(cs + bidx, val);
                    if (auxmode) {
                        const float t = (auxmode == 1) ? val * val
                                                       : fmaf(auxf[idx], auxf[idx], val);
                        st1(ds + bidx, t);
                    }
                }
            }
        }
    }
}

// ---------------------------------------------------------------------------
// batched projection kernels
// ---------------------------------------------------------------------------
__global__ __launch_bounds__(256, 2)
void proj_a_k(half* __restrict__ hp, float* __restrict__ kf, float* __restrict__ vf) {
    const uint16_t* u = (const uint16_t*)hp;
    switch (blockIdx.z) {
    case 0: // q mu -> split qh/ql, q2 = val^2
        gemm_body<128, 0, true, half>(u + HXH, u + HXL, u + WQMH, u + WQML,
            D_, D_, D_, D_, 0, 0, 0, 0, 0, 0, 0, 1.f,
            nullptr, nullptr, hp + HQH, hp + HQL, nullptr, nullptr, hp + HQ2, 1, 0);
        break;
    case 1: // k mu -> split kh/kl + fp32 kf
        gemm_body<128, 0, true, half>(u + HXH, u + HXL, u + WKMH, u + WKML,
            D_, D_, D_, D_, 0, 0, 0, 0, 0, 0, 0, 1.f,
            kf, nullptr, hp + HKH, hp + HKL, nullptr, nullptr, nullptr, 0, 0);
        break;
    case 2: // v mu -> fp32 vf + fp16 transposed vt
        gemm_body<128, 0, true, half>(u + HXH, u + HXL, u + WVMH, u + WVML,
            D_, D_, D_, D_, 0, 0, 0, 0, 0, 0, 0, 1.f,
            vf, nullptr, nullptr, nullptr, hp + HVT, nullptr, nullptr, 0, 1);
        break;
    default: // vq
        gemm_body<128, 1, true, half>(u + HVX, u + HX2, u + WQP, u + WQV,
            D_, D_, D_, D_, 0, 0, 0, 0, 0, 0, 0, 1.f,
            nullptr, nullptr, nullptr, nullptr, hp + HVQ, nullptr, nullptr, 0, 0);
        break;
    }
}

__global__ __launch_bounds__(256, 2)
void proj_b_k(half* __restrict__ hp, bf16* __restrict__ bp,
              const float* __restrict__ kf, const float* __restrict__ vf) {
    const uint16_t* u = (const uint16_t*)hp;
    if (blockIdx.z == 0) { // vk ; vkk = vk + kf^2
        gemm_body<128, 1, true, half>(u + HVX, u + HX2, u + WKP, u + WKV,
            D_, D_, D_, D_, 0, 0, 0, 0, 0, 0, 0, 1.f,
            nullptr, nullptr, nullptr, nullptr, hp + HVK, kf, hp + HVKK, 2, 0);
    } else {               // vv (bf16, transposed) ; vvv = vv + vf^2
        gemm_body<128, 1, true, bf16>(u + HVX, u + HX2, u + WVP, u + WVV,
            D_, D_, D_, D_, 0, 0, 0, 0, 0, 0, 0, 1.f,
            nullptr, nullptr, nullptr, nullptr, bp + BVVT, vf, bp + BVVVT, 2, 1);
    }
}

__global__ __launch_bounds__(256, 2)
void av_k(half* __restrict__ hp, bf16* __restrict__ bp,
          const float* __restrict__ x, float* __restrict__ out) {
    const uint16_t* u = (const uint16_t*)hp;
    const long long sbF = (long long)H_ * S_ * S_, shF = (long long)S_ * S_;
    const long long sbH = (long long)S_ * D_;
    const long long sbVT = (long long)D_ * S_, shVT = (long long)DH_ * S_;
    const int op = blockIdx.z >> 5;
    const int bz = blockIdx.z & 31;
    if (op == 0) {
        gemm_body<64, 2, true, half>(u + HPH, u + HPL, u + HVT, nullptr,
            S_, S_, S_, D_, sbF, shF, sbVT, shVT, sbH, DH_, bz, 1.f,
            out, x, nullptr, nullptr, nullptr, nullptr, nullptr, 0, 0);
    } else {
        gemm_body<64, 1, false, bf16>(
            (const uint16_t*)(bp + BG), (const uint16_t*)(bp + BP2),
            (const uint16_t*)(bp + BVVVT), (const uint16_t*)(bp + BVVT),
            S_, S_, S_, D_, sbF, shF, sbVT, shVT, sbH, DH_, bz, 1.f,
            out + SZ_TOK, nullptr, nullptr, nullptr, nullptr, nullptr, nullptr, 0, 0);
    }
}

// ---------------------------------------------------------------------------
// fused scores + softmax-VDP kernel (unchanged from R5)
// ---------------------------------------------------------------------------
#define SKQ 72
__global__ __launch_bounds__(256)
void scores_k(const uint16_t* __restrict__ qh, const uint16_t* __restrict__ ql,
              const uint16_t* __restrict__ vq, const uint16_t* __restrict__ q2,
              const uint16_t* __restrict__ kh, const uint16_t* __restrict__ kl,
              const uint16_t* __restrict__ vkk, const uint16_t* __restrict__ vk,
              half* __restrict__ ph, half* __restrict__ pl,
              bf16* __restrict__ p2, bf16* __restrict__ g)
{
    constexpr int QT = 16 * SKQ * 2;
    constexpr int KT = 128 * SKQ * 2;
    constexpr int QB = 4 * QT;
    constexpr int KBUF = 4 * KT;
    constexpr int RB = QB + 2 * KBUF;

    extern __shared__ char smem[];
    const uint32_t s32 = smem_to_u32(smem);
    const int tid = threadIdx.x, wid = tid >> 5, lane = tid & 31;
    const int bh = blockIdx.y, bb = bh >> 4, hh = bh & 15;
    const int m0 = blockIdx.x * 16;
    const long long tokOff = (long long)bb * S_ * D_ + (long long)hh * DH_;
    const long long attOff = (long long)bh * ((long long)S_ * S_);

#pragma unroll
    for (int i = 0; i < 2; i++) {
        const int c = tid + i * 256;
        const int arr = c >> 7, r = (c >> 3) & 15, seg = c & 7;
        const uint16_t* src = (arr == 0) ? qh : (arr == 1) ? ql : (arr == 2) ? vq : q2;
        cp16(s32 + arr * QT + (uint32_t)(r * SKQ + seg * 8) * 2,
             src + tokOff + (long long)(m0 + r) * D_ + seg * 8);
    }
    CP_COMMIT();

    auto loadK = [&](int c0, int buf) {
        const uint32_t kb = s32 + QB + buf * KBUF;
#pragma unroll
        for (int i = 0; i < 16; i++) {
            const int c = tid + i * 256;
            const int arr = c >> 10, rr = (c >> 3) & 127, seg = c & 7;
            const uint16_t* src = (arr == 0) ? kh : (arr == 1) ? kl : (arr == 2) ? vkk : vk;
            cp16(kb + arr * KT + (uint32_t)(rr * SKQ + seg * 8) * 2,
                 src + tokOff + (long long)(c0 * 128 + rr) * D_ + seg * 8);
        }
        CP_COMMIT();
    };

    float accS[8][2][4], accVS[8][2][4];
#pragma unroll
    for (int c = 0; c < 8; c++)
#pragma unroll
        for (int nt = 0; nt < 2; nt++)
#pragma unroll
            for (int r = 0; r < 4; r++) { accS[c][nt][r] = 0.f; accVS[c][nt][r] = 0.f; }

    loadK(0, 0);
#pragma unroll
    for (int c0 = 0; c0 < 8; c0++) {
        const int buf = c0 & 1;
        if (c0 + 1 < 8) { loadK(c0 + 1, buf ^ 1); CP_WAIT(1); }
        else            { CP_WAIT(0); }
        __syncthreads();
        const uint32_t kb = s32 + QB + buf * KBUF;
#pragma unroll
        for (int ks = 0; ks < 4; ks++) {
            const int kcol = ks * 16 + (lane >> 4) * 8;
            uint32_t af[4][4];
#pragma unroll
            for (int m = 0; m < 4; m++)
                ldsm4(af[m], s32 + m * QT + (uint32_t)((lane & 15) * SKQ + kcol) * 2);
            uint32_t bfr[4][2][2];
#pragma unroll
            for (int m = 0; m < 4; m++) {
                uint32_t r[4];
                ldsm4(r, kb + m * KT + (uint32_t)((wid * 16 + (lane & 15)) * SKQ + kcol) * 2);
                bfr[m][0][0] = r[0]; bfr[m][0][1] = r[2];
                bfr[m][1][0] = r[1]; bfr[m][1][1] = r[3];
            }
#pragma unroll
            for (int nt = 0; nt < 2; nt++) {
                mma_h(accS[c0][nt],  af[0], bfr[0][nt]);
                mma_h(accS[c0][nt],  af[1], bfr[0][nt]);
                mma_h(accS[c0][nt],  af[0], bfr[1][nt]);
                mma_h(accVS[c0][nt], af[2], bfr[2][nt]);
                mma_h(accVS[c0][nt], af[3], bfr[3][nt]);
            }
        }
        __syncthreads();
    }

    float* red = (float*)(smem + RB);
    const int r0 = lane >> 2;
    const float sscale = 1.0f / 32.0f;
    float mx[2] = {-1e30f, -1e30f};
#pragma unroll
    for (int c = 0; c < 8; c++)
#pragma unroll
        for (int nt = 0; nt < 2; nt++)
#pragma unroll
            for (int rp = 0; rp < 2; rp++)
                mx[rp] = fmaxf(mx[rp], fmaxf(accS[c][nt][rp * 2], accS[c][nt][rp * 2 + 1]));
    mx[0] *= sscale; mx[1] *= sscale;
#pragma unroll
    for (int d = 1; d <= 2; d <<= 1) {
        mx[0] = fmaxf(mx[0], __shfl_xor_sync(0xffffffff, mx[0], d));
        mx[1] = fmaxf(mx[1], __shfl_xor_sync(0xffffffff, mx[1], d));
    }
    if ((lane & 3) == 0) {
        red[r0 * 8 + wid] = mx[0];
        red[(r0 + 8) * 8 + wid] = mx[1];
    }
    __syncthreads();
    float rmx[2];
#pragma unroll
    for (int rp = 0; rp < 2; rp++) {
        float v = -1e30f;
#pragma unroll
        for (int w = 0; w < 8; w++) v = fmaxf(v, red[(r0 + rp * 8) * 8 + w]);
        rmx[rp] = v;
    }
    __syncthreads();
    float sm[2] = {0.f, 0.f};
#pragma unroll
    for (int c = 0; c < 8; c++)
#pragma unroll
        for (int nt = 0; nt < 2; nt++)
#pragma unroll
            for (int rp = 0; rp < 2; rp++)
#pragma unroll
                for (int cc = 0; cc < 2; cc++) {
                    float e = __expf(accS[c][nt][rp * 2 + cc] * sscale - rmx[rp]);
                    accS[c][nt][rp * 2 + cc] = e;
                    sm[rp] += e;
                }
#pragma unroll
    for (int d = 1; d <= 2; d <<= 1) {
        sm[0] += __shfl_xor_sync(0xffffffff, sm[0], d);
        sm[1] += __shfl_xor_sync(0xffffffff, sm[1], d);
    }
    if ((lane & 3) == 0) {
        red[r0 * 8 + wid] = sm[0];
        red[(r0 + 8) * 8 + wid] = sm[1];
    }
    __syncthreads();
    float inv[2];
#pragma unroll
    for (int rp = 0; rp < 2; rp++) {
        float v = 0.f;
#pragma unroll
        for (int w = 0; w < 8; w++) v += red[(r0 + rp * 8) * 8 + w];
        inv[rp] = 1.0f / v;
    }

    const float vscale = 1.0f / 1024.0f;
#pragma unroll
    for (int c = 0; c < 8; c++)
#pragma unroll
        for (int nt = 0; nt < 2; nt++)
#pragma unroll
            for (int rp = 0; rp < 2; rp++)
#pragma unroll
                for (int cc = 0; cc < 2; cc++) {
                    const int col = c * 128 + wid * 16 + nt * 8 + (lane & 3) * 2 + cc;
                    const int row = m0 + r0 + rp * 8;
                    const long long idx = attOff + (long long)row * S_ + col;
                    const float p = accS[c][nt][rp * 2 + cc] * inv[rp];
                    half hp_ = __float2half(p);
                    ph[idx] = hp_;
                    pl[idx] = __float2half(p - __half2float(hp_));
                    const float vs = accVS[c][nt][rp * 2 + cc] * vscale;
                    const float pm = p * (1.0f - p);
                    p2[idx] = __float2bfloat16(p * p);
                    g[idx]  = __float2bfloat16(pm * pm * vs);
                }
}

// ---------------------------------------------------------------------------
extern "C" void kernel_launch(void* const* d_in, const int* in_sizes, int n_in,
                              void* d_out, int out_size)
{
    (void)in_sizes; (void)n_in; (void)out_size;
    const float* x      = (const float*)d_in[0];
    const float* var_x  = (const float*)d_in[1];
    const float* wq_mu  = (const float*)d_in[2];
    const float* wq_var = (const float*)d_in[3];
    const float* wk_mu  = (const float*)d_in[4];
    const float* wk_var = (const float*)d_in[5];
    const float* wv_mu  = (const float*)d_in[6];
    const float* wv_var = (const float*)d_in[7];
    float* out = (float*)d_out;

    half* hp = nullptr;  cudaGetSymbolAddress((void**)&hp, g_h);
    bf16* bp = nullptr;  cudaGetSymbolAddress((void**)&bp, g_b);
    float* kf = nullptr; cudaGetSymbolAddress((void**)&kf, g_kf);
    float* vf = nullptr; cudaGetSymbolAddress((void**)&vf, g_vf);

    const int SM128 = 81920;   // 2 bufs x (2*ATILE + 2*BTILE), BM=BN=128
    const int SM64  = 61440;   // BN=64, NMATB=2 worst case
    const int SMSC  = 9216 + 2 * 73728 + 512;
    cudaFuncSetAttribute(proj_a_k, cudaFuncAttributeMaxDynamicSharedMemorySize, SM128);
    cudaFuncSetAttribute(proj_b_k, cudaFuncAttributeMaxDynamicSharedMemorySize, SM128);
    cudaFuncSetAttribute(av_k,     cudaFuncAttributeMaxDynamicSharedMemorySize, SM64);
    cudaFuncSetAttribute(scores_k, cudaFuncAttributeMaxDynamicSharedMemorySize, SMSC);

    conv_all_k<<<(int)(SZ_TOK / 256), 256>>>(x, var_x, wq_mu, wq_var, wk_mu, wk_var,
                                             wv_mu, wv_var, hp);

    proj_a_k<<<dim3(8, 16, 4), 256, SM128>>>(hp, kf, vf);
    proj_b_k<<<dim3(8, 16, 2), 256, SM128>>>(hp, bp, kf, vf);

    const uint16_t* u = (const uint16_t*)hp;
    scores_k<<<dim3(64, 32), 256, SMSC>>>(
        u + HQH, u + HQL, u + HVQ, u + HQ2,
        u + HKH, u + HKL, u + HVKK, u + HVK,
        hp + HPH, hp + HPL, bp + BP2, bp + BG);

    av_k<<<dim3(1, 8, 64), 256, SM64>>>(hp, bp, x, out);
}

// round 7
// speedup vs baseline: 3.3427x; 1.1757x over previous
#include <cuda_runtime.h>
#include <cuda_bf16.h>
#include <cuda_fp16.h>
#include <cstdint>

typedef __nv_bfloat16 bf16;

#define B_  2
#define S_  1024
#define D_  1024
#define H_  16
#define DH_ 64

static const long long SZ_TOK = 2097152LL;
static const long long SZ_W   = 1048576LL;
static const long long SZ_ATT = 33554432LL;

// ---- half pool offsets (elements) ----
#define HXH   (0LL  * SZ_TOK)
#define HXL   (1LL  * SZ_TOK)
#define HX2   (2LL  * SZ_TOK)
#define HVX   (3LL  * SZ_TOK)
#define HQH   (4LL  * SZ_TOK)
#define HQL   (5LL  * SZ_TOK)
#define HQ2   (6LL  * SZ_TOK)
#define HKH   (7LL  * SZ_TOK)
#define HKL   (8LL  * SZ_TOK)
#define HVT   (9LL  * SZ_TOK)
#define HVQ   (10LL * SZ_TOK)
#define HVK   (11LL * SZ_TOK)
#define HVKK  (12LL * SZ_TOK)
#define HW0   (13LL * SZ_TOK)
#define WQMH  (HW0 + 0LL  * SZ_W)
#define WQML  (HW0 + 1LL  * SZ_W)
#define WQV   (HW0 + 2LL  * SZ_W)
#define WQP   (HW0 + 3LL  * SZ_W)
#define WKMH  (HW0 + 4LL  * SZ_W)
#define WKML  (HW0 + 5LL  * SZ_W)
#define WKV   (HW0 + 6LL  * SZ_W)
#define WKP   (HW0 + 7LL  * SZ_W)
#define WVMH  (HW0 + 8LL  * SZ_W)
#define WVML  (HW0 + 9LL  * SZ_W)
#define WVV   (HW0 + 10LL * SZ_W)
#define WVP   (HW0 + 11LL * SZ_W)
#define HPH   (HW0 + 12LL * SZ_W)
#define HPL   (HPH + SZ_ATT)
#define H_TOTAL (HPL + SZ_ATT)

// ---- bf16 pool offsets ----
#define BP2   (0LL)
#define BG    (1LL * SZ_ATT)
#define BVVT  (2LL * SZ_ATT)
#define BVVVT (2LL * SZ_ATT + SZ_TOK)
#define B_TOTAL (2LL * SZ_ATT + 2LL * SZ_TOK)

__device__ half  g_h[H_TOTAL];
__device__ bf16  g_b[B_TOTAL];
__device__ float g_kf[SZ_TOK];
__device__ float g_vf[SZ_TOK];

// ---------------------------------------------------------------------------
__device__ __forceinline__ uint32_t smem_to_u32(const void* p) {
    uint32_t a;
    asm("{ .reg .u64 t; cvta.to.shared.u64 t, %1; cvt.u32.u64 %0, t; }" : "=r"(a) : "l"(p));
    return a;
}
__device__ __forceinline__ void cp16(uint32_t s, const void* g) {
    asm volatile("cp.async.cg.shared.global [%0], [%1], 16;" :: "r"(s), "l"(g) : "memory");
}
#define CP_COMMIT() asm volatile("cp.async.commit_group;" ::: "memory")
#define CP_WAIT(n)  asm volatile("cp.async.wait_group %0;" :: "n"(n) : "memory")

__device__ __forceinline__ void ldsm4(uint32_t* r, uint32_t addr) {
    asm volatile("ldmatrix.sync.aligned.m8n8.x4.shared.b16 {%0,%1,%2,%3}, [%4];"
        : "=r"(r[0]), "=r"(r[1]), "=r"(r[2]), "=r"(r[3]) : "r"(addr));
}
__device__ __forceinline__ void ldsm2(uint32_t* r, uint32_t addr) {
    asm volatile("ldmatrix.sync.aligned.m8n8.x2.shared.b16 {%0,%1}, [%2];"
        : "=r"(r[0]), "=r"(r[1]) : "r"(addr));
}
__device__ __forceinline__ void mma_h(float* c, const uint32_t* a, const uint32_t* b) {
    asm volatile(
        "mma.sync.aligned.m16n8k16.row.col.f32.f16.f16.f32 "
        "{%0,%1,%2,%3}, {%4,%5,%6,%7}, {%8,%9}, {%0,%1,%2,%3};"
        : "+f"(c[0]), "+f"(c[1]), "+f"(c[2]), "+f"(c[3])
        : "r"(a[0]), "r"(a[1]), "r"(a[2]), "r"(a[3]), "r"(b[0]), "r"(b[1]));
}
__device__ __forceinline__ void mma_b(float* c, const uint32_t* a, const uint32_t* b) {
    asm volatile(
        "mma.sync.aligned.m16n8k16.row.col.f32.bf16.bf16.f32 "
        "{%0,%1,%2,%3}, {%4,%5,%6,%7}, {%8,%9}, {%0,%1,%2,%3};"
        : "+f"(c[0]), "+f"(c[1]), "+f"(c[2]), "+f"(c[3])
        : "r"(a[0]), "r"(a[1]), "r"(a[2]), "r"(a[3]), "r"(b[0]), "r"(b[1]));
}
__device__ __forceinline__ void hsplit(float a, half* h, half* l) {
    half hh = __float2half(a);
    *h = hh; *l = __float2half(a - __half2float(hh));
}
__device__ __forceinline__ void st1(half* p, float v) { *p = __float2half(v); }
__device__ __forceinline__ void st1(bf16* p, float v) { *p = __float2bfloat16(v); }
__device__ __forceinline__ void stsp(half* h, half* l, float v) { hsplit(v, h, l); }
__device__ __forceinline__ void stsp(bf16* h, bf16* l, float v) {
    bf16 hh = __float2bfloat16(v);
    *h = hh; *l = __float2bfloat16(v - __bfloat162float(hh));
}
__device__ __forceinline__ uint32_t pkh(float a, float b) {
    return (uint32_t)__half_as_ushort(__float2half(a)) |
           ((uint32_t)__half_as_ushort(__float2half(b)) << 16);
}
__device__ __forceinline__ uint32_t pkb(float a, float b) {
    return (uint32_t)__bfloat16_as_ushort(__float2bfloat16(a)) |
           ((uint32_t)__bfloat16_as_ushort(__float2bfloat16(b)) << 16);
}

// ---------------------------------------------------------------------------
__global__ void conv_all_k(const float* __restrict__ x, const float* __restrict__ vx,
                           const float* __restrict__ wqm, const float* __restrict__ wqv,
                           const float* __restrict__ wkm, const float* __restrict__ wkv,
                           const float* __restrict__ wvm, const float* __restrict__ wvv,
                           half* __restrict__ hp) {
    const int i = blockIdx.x * 256 + threadIdx.x;
    if (i < (int)SZ_TOK) {
        float a = x[i];
        hsplit(a, hp + HXH + i, hp + HXL + i);
        hp[HX2 + i] = __float2half(a * a);
        hp[HVX + i] = __float2half(vx[i]);
    }
    if (i < (int)SZ_W) {
        float m, v;
        m = wqm[i]; v = wqv[i];
        hsplit(m, hp + WQMH + i, hp + WQML + i);
        hp[WQV + i] = __float2half(v);
        hp[WQP + i] = __float2half(fmaf(m, m, v));
        m = wkm[i]; v = wkv[i];
        hsplit(m, hp + WKMH + i, hp + WKML + i);
        hp[WKV + i] = __float2half(v);
        hp[WKP + i] = __float2half(fmaf(m, m, v));
        m = wvm[i]; v = wvv[i];
        hsplit(m, hp + WVMH + i, hp + WVML + i);
        hp[WVV + i] = __float2half(v);
        hp[WVP + i] = __float2half(fmaf(m, m, v));
    }
}

// ---------------------------------------------------------------------------
// GEMM body (unchanged from R6)
// ---------------------------------------------------------------------------
template<int BN, int MODE, bool F16, typename OT>
__device__ __forceinline__
void gemm_body(const uint16_t* __restrict__ A0, const uint16_t* __restrict__ A1,
               const uint16_t* __restrict__ B0, const uint16_t* __restrict__ B1,
               int K, int lda, int ldb, int ldc,
               long long sbA, long long shA, long long sbB, long long shB,
               long long sbC, long long shC, int bz,
               float alpha,
               float* __restrict__ cf, const float* __restrict__ addp,
               OT* __restrict__ ch, OT* __restrict__ cl, OT* __restrict__ cs,
               const float* __restrict__ auxf, OT* __restrict__ ds, int auxmode,
               int transC)
{
    constexpr int BM = 128, BK = 32, SK = 40;
    constexpr int NMATB = (MODE == 2) ? 1 : 2;
    constexpr int WARPS_N = (BN == 128) ? 4 : 2;
    constexpr int WARPS_M = 8 / WARPS_N;
    constexpr int WM = BM / WARPS_M, WN = BN / WARPS_N;
    constexpr int MT = WM / 16, NT = WN / 8;
    constexpr int ATILE = BM * SK * 2;
    constexpr int BTILE = BN * SK * 2;
    constexpr int BUFB  = 2 * ATILE + NMATB * BTILE;

    extern __shared__ char smem[];
    const uint32_t s32 = smem_to_u32(smem);
    const int tid = threadIdx.x;
    const int wid = tid >> 5, lane = tid & 31;
    const int wm = wid / WARPS_N, wn = wid % WARPS_N;

    const int bb = bz >> 4, hh = bz & 15;
    const long long offA = (long long)bb * sbA + (long long)hh * shA;
    const long long offB = (long long)bb * sbB + (long long)hh * shB;
    const long long offC = (long long)bb * sbC + (long long)hh * shC;
    const int m0 = blockIdx.y * BM;
    const int n0 = blockIdx.x * BN;

    auto loadbuf = [&](int kc, int buf) {
        const int k0 = kc * BK;
        const uint32_t b32 = s32 + buf * BUFB;
#pragma unroll
        for (int i = 0; i < BM * 4 / 256; i++) {
            const int c = tid + i * 256;
            const int row = c >> 2, seg = c & 3;
            const long long go = offA + (long long)(m0 + row) * lda + k0 + seg * 8;
            const uint32_t so = (uint32_t)(row * SK + seg * 8) * 2;
            cp16(b32 + so, A0 + go);
            cp16(b32 + ATILE + so, A1 + go);
        }
#pragma unroll
        for (int i = 0; i < BN * 4 / 256; i++) {
            const int c = tid + i * 256;
            const int row = c >> 2, seg = c & 3;
            const long long go = offB + (long long)(n0 + row) * ldb + k0 + seg * 8;
            const uint32_t so = (uint32_t)(row * SK + seg * 8) * 2;
            cp16(b32 + 2 * ATILE + so, B0 + go);
            if (NMATB == 2) cp16(b32 + 2 * ATILE + BTILE + so, B1 + go);
        }
        CP_COMMIT();
    };

    float acc[MT][NT][4];
#pragma unroll
    for (int i = 0; i < MT; i++)
#pragma unroll
        for (int j = 0; j < NT; j++)
#pragma unroll
            for (int r = 0; r < 4; r++) acc[i][j][r] = 0.f;

    const int NKC = K / BK;
    loadbuf(0, 0);

    for (int kc = 0; kc < NKC; kc++) {
        const int buf = kc & 1;
        if (kc + 1 < NKC) { loadbuf(kc + 1, buf ^ 1); CP_WAIT(1); }
        else              { CP_WAIT(0); }
        __syncthreads();

        const uint32_t b32 = s32 + buf * BUFB;
#pragma unroll
        for (int kh = 0; kh < 2; kh++) {
            const int kcol = kh * 16 + (lane >> 4) * 8;
            uint32_t afr[2][MT][4];
            uint32_t bfr[NMATB][NT][2];
#pragma unroll
            for (int mat = 0; mat < 2; mat++)
#pragma unroll
                for (int mt = 0; mt < MT; mt++) {
                    const int row = wm * WM + mt * 16 + (lane & 15);
                    ldsm4(afr[mat][mt], b32 + mat * ATILE + (uint32_t)(row * SK + kcol) * 2);
                }
#pragma unroll
            for (int mat = 0; mat < NMATB; mat++)
#pragma unroll
                for (int nt2 = 0; nt2 < NT / 2; nt2++) {
                    const int row = wn * WN + nt2 * 16 + (lane & 15);
                    uint32_t r[4];
                    ldsm4(r, b32 + 2 * ATILE + mat * BTILE + (uint32_t)(row * SK + kcol) * 2);
                    bfr[mat][2 * nt2][0]     = r[0]; bfr[mat][2 * nt2][1]     = r[2];
                    bfr[mat][2 * nt2 + 1][0] = r[1]; bfr[mat][2 * nt2 + 1][1] = r[3];
                }

#define DO_MMA(AM, BM_) \
            for (int mt = 0; mt < MT; mt++) \
                for (int nt = 0; nt < NT; nt++) { \
                    if (F16) mma_h(acc[mt][nt], afr[AM][mt], bfr[BM_][nt]); \
                    else     mma_b(acc[mt][nt], afr[AM][mt], bfr[BM_][nt]); \
                }
            DO_MMA(0, 0)
            if (MODE == 0) { DO_MMA(1, 0) DO_MMA(0, 1) }
            else if (MODE == 1) { DO_MMA(1, 1) }
            else { DO_MMA(1, 0) }
#undef DO_MMA
        }
        __syncthreads();
    }

#pragma unroll
    for (int mt = 0; mt < MT; mt++) {
#pragma unroll
        for (int nt = 0; nt < NT; nt++) {
#pragma unroll
            for (int rp = 0; rp < 2; rp++) {
                const int m = m0 + wm * WM + mt * 16 + (lane >> 2) + rp * 8;
                const int nbase = n0 + wn * WN + nt * 8 + (lane & 3) * 2;
#pragma unroll
                for (int cc = 0; cc < 2; cc++) {
                    const int n = nbase + cc;
                    float val = alpha * acc[mt][nt][rp * 2 + cc];
                    const long long idx = offC + (long long)m * ldc + n;
                    if (addp) val += addp[idx];
                    if (cf) cf[idx] = val;
                    const long long bidx = transC
                        ? ((long long)(m >> 10) * ((long long)D_ * S_) + (long long)n * S_ + (m & (S_ - 1)))
                        : idx;
                    if (ch) stsp(ch + bidx, cl + bidx, val);
                    if (cs) st1(cs + bidx, val);
                    if (auxmode) {
                        const float t = (auxmode == 1) ? val * val
                                                       : fmaf(auxf[idx], auxf[idx], val);
                        st1(ds + bidx, t);
                    }
                }
            }
        }
    }
}

// ---------------------------------------------------------------------------
__global__ __launch_bounds__(256, 2)
void proj_a_k(half* __restrict__ hp, float* __restrict__ kf, float* __restrict__ vf) {
    const uint16_t* u = (const uint16_t*)hp;
    switch (blockIdx.z) {
    case 0:
        gemm_body<128, 0, true, half>(u + HXH, u + HXL, u + WQMH, u + WQML,
            D_, D_, D_, D_, 0, 0, 0, 0, 0, 0, 0, 1.f,
            nullptr, nullptr, hp + HQH, hp + HQL, nullptr, nullptr, hp + HQ2, 1, 0);
        break;
    case 1:
        gemm_body<128, 0, true, half>(u + HXH, u + HXL, u + WKMH, u + WKML,
            D_, D_, D_, D_, 0, 0, 0, 0, 0, 0, 0, 1.f,
            kf, nullptr, hp + HKH, hp + HKL, nullptr, nullptr, nullptr, 0, 0);
        break;
    case 2:
        gemm_body<128, 0, true, half>(u + HXH, u + HXL, u + WVMH, u + WVML,
            D_, D_, D_, D_, 0, 0, 0, 0, 0, 0, 0, 1.f,
            vf, nullptr, nullptr, nullptr, hp + HVT, nullptr, nullptr, 0, 1);
        break;
    default:
        gemm_body<128, 1, true, half>(u + HVX, u + HX2, u + WQP, u + WQV,
            D_, D_, D_, D_, 0, 0, 0, 0, 0, 0, 0, 1.f,
            nullptr, nullptr, nullptr, nullptr, hp + HVQ, nullptr, nullptr, 0, 0);
        break;
    }
}

__global__ __launch_bounds__(256, 2)
void proj_b_k(half* __restrict__ hp, bf16* __restrict__ bp,
              const float* __restrict__ kf, const float* __restrict__ vf) {
    const uint16_t* u = (const uint16_t*)hp;
    if (blockIdx.z == 0) {
        gemm_body<128, 1, true, half>(u + HVX, u + HX2, u + WKP, u + WKV,
            D_, D_, D_, D_, 0, 0, 0, 0, 0, 0, 0, 1.f,
            nullptr, nullptr, nullptr, nullptr, hp + HVK, kf, hp + HVKK, 2, 0);
    } else {
        gemm_body<128, 1, true, bf16>(u + HVX, u + HX2, u + WVP, u + WVV,
            D_, D_, D_, D_, 0, 0, 0, 0, 0, 0, 0, 1.f,
            nullptr, nullptr, nullptr, nullptr, bp + BVVT, vf, bp + BVVVT, 2, 1);
    }
}

__global__ __launch_bounds__(256, 2)
void av_k(half* __restrict__ hp, bf16* __restrict__ bp,
          const float* __restrict__ x, float* __restrict__ out) {
    const uint16_t* u = (const uint16_t*)hp;
    const long long sbF = (long long)H_ * S_ * S_, shF = (long long)S_ * S_;
    const long long sbH = (long long)S_ * D_;
    const long long sbVT = (long long)D_ * S_, shVT = (long long)DH_ * S_;
    const int op = blockIdx.z >> 5;
    const int bz = blockIdx.z & 31;
    if (op == 0) {
        gemm_body<64, 2, true, half>(u + HPH, u + HPL, u + HVT, nullptr,
            S_, S_, S_, D_, sbF, shF, sbVT, shVT, sbH, DH_, bz, 1.f,
            out, x, nullptr, nullptr, nullptr, nullptr, nullptr, 0, 0);
    } else {
        gemm_body<64, 1, false, bf16>(
            (const uint16_t*)(bp + BG), (const uint16_t*)(bp + BP2),
            (const uint16_t*)(bp + BVVVT), (const uint16_t*)(bp + BVVT),
            S_, S_, S_, D_, sbF, shF, sbVT, shVT, sbH, DH_, bz, 1.f,
            out + SZ_TOK, nullptr, nullptr, nullptr, nullptr, nullptr, nullptr, 0, 0);
    }
}

// ---------------------------------------------------------------------------
// R7 scores_k: 16 q-rows x 1024 cols, 64-col K chunks (16, double-buffered),
// VS streamed to global bf16 in-loop (g buffer as scratch), S acc only.
// 8 warps x 8-col strips. 2 CTAs/SM.
// ---------------------------------------------------------------------------
#define SKQ 72
__global__ __launch_bounds__(256, 2)
void scores_k(const uint16_t* __restrict__ qh, const uint16_t* __restrict__ ql,
              const uint16_t* __restrict__ vq, const uint16_t* __restrict__ q2,
              const uint16_t* __restrict__ kh, const uint16_t* __restrict__ kl,
              const uint16_t* __restrict__ vkk, const uint16_t* __restrict__ vk,
              half* __restrict__ ph, half* __restrict__ pl,
              bf16* __restrict__ p2, bf16* __restrict__ g)
{
    constexpr int QT = 16 * SKQ * 2;     // 2304
    constexpr int QB = 4 * QT;           // 9216
    constexpr int KT = 64 * SKQ * 2;     // 9216 per array
    constexpr int KBUF = 4 * KT;         // 36864 per buffer
    constexpr int RB = QB + 2 * KBUF;    // 82944

    extern __shared__ char smem[];
    const uint32_t s32 = smem_to_u32(smem);
    const int tid = threadIdx.x, wid = tid >> 5, lane = tid & 31;
    const int bh = blockIdx.y, bb = bh >> 4, hh = bh & 15;
    const int m0 = blockIdx.x * 16;
    const long long tokOff = (long long)bb * S_ * D_ + (long long)hh * DH_;
    const long long attOff = (long long)bh * ((long long)S_ * S_);
    const float vscale = 1.0f / 1024.0f;

    // Q tiles: 4 arrays x 16 rows x 64 cols
#pragma unroll
    for (int i = 0; i < 2; i++) {
        const int c = tid + i * 256;
        const int arr = c >> 7, r = (c >> 3) & 15, seg = c & 7;
        const uint16_t* src = (arr == 0) ? qh : (arr == 1) ? ql : (arr == 2) ? vq : q2;
        cp16(s32 + arr * QT + (uint32_t)(r * SKQ + seg * 8) * 2,
             src + tokOff + (long long)(m0 + r) * D_ + seg * 8);
    }
    CP_COMMIT();

    auto loadK = [&](int c0, int buf) {
        const uint32_t kb = s32 + QB + buf * KBUF;
#pragma unroll
        for (int i = 0; i < 8; i++) {
            const int c = tid + i * 256;                 // 2048 cp16 total
            const int arr = c >> 9, rr = (c >> 3) & 63, seg = c & 7;
            const uint16_t* src = (arr == 0) ? kh : (arr == 1) ? kl : (arr == 2) ? vkk : vk;
            cp16(kb + arr * KT + (uint32_t)(rr * SKQ + seg * 8) * 2,
                 src + tokOff + (long long)(c0 * 64 + rr) * D_ + seg * 8);
        }
        CP_COMMIT();
    };

    float acc[16][4];
#pragma unroll
    for (int c = 0; c < 16; c++)
#pragma unroll
        for (int r = 0; r < 4; r++) acc[c][r] = 0.f;

    const int r0 = lane >> 2;           // epilogue row-in-halfgroup
    const int colq = (lane & 3) * 2;    // epilogue col pair base

    loadK(0, 0);
#pragma unroll
    for (int c0 = 0; c0 < 16; c0++) {
        const int buf = c0 & 1;
        if (c0 + 1 < 16) { loadK(c0 + 1, buf ^ 1); CP_WAIT(1); }
        else             { CP_WAIT(0); }
        __syncthreads();
        const uint32_t kb = s32 + QB + buf * KBUF;

        float accVS[4] = {0.f, 0.f, 0.f, 0.f};
#pragma unroll
        for (int ks = 0; ks < 4; ks++) {
            const int kcolA = ks * 16 + (lane >> 4) * 8;
            uint32_t af[4][4];
#pragma unroll
            for (int m = 0; m < 4; m++)
                ldsm4(af[m], s32 + m * QT + (uint32_t)((lane & 15) * SKQ + kcolA) * 2);
            // B frags: 8-row strip, ldsm.x2 (lanes 0-15 addresses used)
            const int brow = wid * 8 + (lane & 7);
            const int bkoff = ks * 16 + ((lane >> 3) & 1) * 8;
            uint32_t bf[4][2];
#pragma unroll
            for (int m = 0; m < 4; m++)
                ldsm2(bf[m], kb + m * KT + (uint32_t)(brow * SKQ + bkoff) * 2);

            mma_h(acc[c0], af[0], bf[0]);   // qh.kh
            mma_h(acc[c0], af[1], bf[0]);   // ql.kh
            mma_h(acc[c0], af[0], bf[1]);   // qh.kl
            mma_h(accVS,   af[2], bf[2]);   // vq.vkk
            mma_h(accVS,   af[3], bf[3]);   // q2.vk
        }
        // stream VS out (scaled), packed bf16x2; re-read by same thread later
#pragma unroll
        for (int rp = 0; rp < 2; rp++) {
            const int row = m0 + r0 + rp * 8;
            const int col = c0 * 64 + wid * 8 + colq;
            const long long idx = attOff + (long long)row * S_ + col;
            *(uint32_t*)(g + idx) = pkb(accVS[rp * 2] * vscale, accVS[rp * 2 + 1] * vscale);
        }
        __syncthreads();
    }

    // ---- softmax over rows ----
    float* red = (float*)(smem + RB);  // [16][8]
    const float sscale = 1.0f / 32.0f;
    float mx[2] = {-1e30f, -1e30f};
#pragma unroll
    for (int c = 0; c < 16; c++)
#pragma unroll
        for (int rp = 0; rp < 2; rp++)
            mx[rp] = fmaxf(mx[rp], fmaxf(acc[c][rp * 2], acc[c][rp * 2 + 1]));
    mx[0] *= sscale; mx[1] *= sscale;
#pragma unroll
    for (int d = 1; d <= 2; d <<= 1) {
        mx[0] = fmaxf(mx[0], __shfl_xor_sync(0xffffffff, mx[0], d));
        mx[1] = fmaxf(mx[1], __shfl_xor_sync(0xffffffff, mx[1], d));
    }
    if ((lane & 3) == 0) {
        red[r0 * 8 + wid] = mx[0];
        red[(r0 + 8) * 8 + wid] = mx[1];
    }
    __syncthreads();
    float rmx[2];
#pragma unroll
    for (int rp = 0; rp < 2; rp++) {
        float v = -1e30f;
#pragma unroll
        for (int w = 0; w < 8; w++) v = fmaxf(v, red[(r0 + rp * 8) * 8 + w]);
        rmx[rp] = v;
    }
    __syncthreads();
    float sm[2] = {0.f, 0.f};
#pragma unroll
    for (int c = 0; c < 16; c++)
#pragma unroll
        for (int rp = 0; rp < 2; rp++)
#pragma unroll
            for (int cc = 0; cc < 2; cc++) {
                float e = __expf(acc[c][rp * 2 + cc] * sscale - rmx[rp]);
                acc[c][rp * 2 + cc] = e;
                sm[rp] += e;
            }
#pragma unroll
    for (int d = 1; d <= 2; d <<= 1) {
        sm[0] += __shfl_xor_sync(0xffffffff, sm[0], d);
        sm[1] += __shfl_xor_sync(0xffffffff, sm[1], d);
    }
    if ((lane & 3) == 0) {
        red[r0 * 8 + wid] = sm[0];
        red[(r0 + 8) * 8 + wid] = sm[1];
    }
    __syncthreads();
    float inv[2];
#pragma unroll
    for (int rp = 0; rp < 2; rp++) {
        float v = 0.f;
#pragma unroll
        for (int w = 0; w < 8; w++) v += red[(r0 + rp * 8) * 8 + w];
        inv[rp] = 1.0f / v;
    }

    // ---- outputs: p (split fp16), p2 (bf16), g = pm^2 * vs (bf16, read back) ----
#pragma unroll
    for (int c = 0; c < 16; c++)
#pragma unroll
        for (int rp = 0; rp < 2; rp++) {
            const int row = m0 + r0 + rp * 8;
            const int col = c * 64 + wid * 8 + colq;
            const long long idx = attOff + (long long)row * S_ + col;
            float p0 = acc[c][rp * 2] * inv[rp];
            float p1 = acc[c][rp * 2 + 1] * inv[rp];
            // p split
            half h0 = __float2half(p0), h1 = __float2half(p1);
            *(uint32_t*)(ph + idx) = (uint32_t)__half_as_ushort(h0) |
                                     ((uint32_t)__half_as_ushort(h1) << 16);
            *(uint32_t*)(pl + idx) = pkh(p0 - __half2float(h0), p1 - __half2float(h1));
            // p^2
            *(uint32_t*)(p2 + idx) = pkb(p0 * p0, p1 * p1);
            // g
            const uint32_t vsp = *(const uint32_t*)(g + idx);
            const float vs0 = __bfloat162float(__ushort_as_bfloat16((unsigned short)(vsp & 0xffff)));
            const float vs1 = __bfloat162float(__ushort_as_bfloat16((unsigned short)(vsp >> 16)));
            const float pm0 = p0 * (1.0f - p0), pm1 = p1 * (1.0f - p1);
            *(uint32_t*)(g + idx) = pkb(pm0 * pm0 * vs0, pm1 * pm1 * vs1);
        }
}

// ---------------------------------------------------------------------------
extern "C" void kernel_launch(void* const* d_in, const int* in_sizes, int n_in,
                              void* d_out, int out_size)
{
    (void)in_sizes; (void)n_in; (void)out_size;
    const float* x      = (const float*)d_in[0];
    const float* var_x  = (const float*)d_in[1];
    const float* wq_mu  = (const float*)d_in[2];
    const float* wq_var = (const float*)d_in[3];
    const float* wk_mu  = (const float*)d_in[4];
    const float* wk_var = (const float*)d_in[5];
    const float* wv_mu  = (const float*)d_in[6];
    const float* wv_var = (const float*)d_in[7];
    float* out = (float*)d_out;

    half* hp = nullptr;  cudaGetSymbolAddress((void**)&hp, g_h);
    bf16* bp = nullptr;  cudaGetSymbolAddress((void**)&bp, g_b);
    float* kf = nullptr; cudaGetSymbolAddress((void**)&kf, g_kf);
    float* vf = nullptr; cudaGetSymbolAddress((void**)&vf, g_vf);

    const int SM128 = 81920;
    const int SM64  = 61440;
    const int SMSC  = 9216 + 2 * 36864 + 512;  // 83456
    cudaFuncSetAttribute(proj_a_k, cudaFuncAttributeMaxDynamicSharedMemorySize, SM128);
    cudaFuncSetAttribute(proj_b_k, cudaFuncAttributeMaxDynamicSharedMemorySize, SM128);
    cudaFuncSetAttribute(av_k,     cudaFuncAttributeMaxDynamicSharedMemorySize, SM64);
    cudaFuncSetAttribute(scores_k, cudaFuncAttributeMaxDynamicSharedMemorySize, SMSC);

    conv_all_k<<<(int)(SZ_TOK / 256), 256>>>(x, var_x, wq_mu, wq_var, wk_mu, wk_var,
                                             wv_mu, wv_var, hp);

    proj_a_k<<<dim3(8, 16, 4), 256, SM128>>>(hp, kf, vf);
    proj_b_k<<<dim3(8, 16, 2), 256, SM128>>>(hp, bp, kf, vf);

    const uint16_t* u = (const uint16_t*)hp;
    scores_k<<<dim3(64, 32), 256, SMSC>>>(
        u + HQH, u + HQL, u + HVQ, u + HQ2,
        u + HKH, u + HKL, u + HVKK, u + HVK,
        hp + HPH, hp + HPL, bp + BP2, bp + BG);

    av_k<<<dim3(1, 8, 64), 256, SM64>>>(hp, bp, x, out);
}